// round 3
// baseline (speedup 1.0000x reference)
#include <cuda_runtime.h>
#include <cstdint>

#define BATCH   2048
#define NTOK    64
#define DIM     256
#define HEADS   8
#define HEADDIM 32
#define MASK_NW 64

// Combined mask + gathered relative bias: [window][head][64*64]
__device__ float g_CMB[(size_t)MASK_NW * HEADS * NTOK * NTOK];

__device__ __forceinline__ float f2tf32(float x) {
    float r;
    asm("cvt.rna.tf32.f32 %0, %1;" : "=f"(r) : "f"(x));
    return r;
}
__device__ __forceinline__ uint32_t fbits(float x) { return __float_as_uint(x); }

__device__ __forceinline__ void mma8(float* d, const uint32_t* a, const uint32_t* b) {
    asm("mma.sync.aligned.m16n8k8.row.col.f32.tf32.tf32.f32 "
        "{%0,%1,%2,%3}, {%4,%5,%6,%7}, {%8,%9}, {%0,%1,%2,%3};"
        : "+f"(d[0]), "+f"(d[1]), "+f"(d[2]), "+f"(d[3])
        : "r"(a[0]), "r"(a[1]), "r"(a[2]), "r"(a[3]), "r"(b[0]), "r"(b[1]));
}

// ---------------------------------------------------------------------------
// Kernel 0: precompute combined mask + relative-position bias.
// ---------------------------------------------------------------------------
__global__ void prep_cmb(const float* __restrict__ mask,
                         const float* __restrict__ bt,
                         const int*   __restrict__ ri)
{
    const int idx = blockIdx.x * 256 + threadIdx.x;
    const int p = idx & 4095;
    const int h = (idx >> 12) & 7;
    const int w = idx >> 15;
    g_CMB[idx] = mask[w * 4096 + p] + bt[ri[p] * 8 + h];
}

// ---------------------------------------------------------------------------
// Fused kernel: one CTA per window (64 tokens). 256 threads = 8 warps.
// Loop over 4 head-pairs: QKV GEMM (64x192x256, tf32 mma, streamed weights)
// -> smem QKV tiles -> attention (scores + softmax + PV) -> output.
//
// smem (floats):
//   [0, 16640)       X tile   64 x 260 (tf32)
//   [16640, 30464)   W double buffer 2 x (192 x 36)  | aliased by scores
//                    sc = 2 heads x (64 x 68) = 8704 floats
//   [30464, 44800)   QKV tiles: 2 heads x (Q 64x36, K 64x36, V 64x40)
// total 44800 floats = 179200 B
// ---------------------------------------------------------------------------
#define SMEM_FLOATS 44800
#define XOFF   0
#define WOFF   16640
#define QKVOFF 30464

__global__ __launch_bounds__(256, 1) void fused_qkv_attn(
    const float* __restrict__ X,
    const float* __restrict__ Wq, const float* __restrict__ Bq,
    const float* __restrict__ Wk, const float* __restrict__ Bk,
    const float* __restrict__ Wv, const float* __restrict__ Bv,
    float* __restrict__ out)
{
    extern __shared__ float sm[];
    float* sm_x   = sm + XOFF;     // stride 260
    float* sm_w   = sm + WOFF;     // 2 bufs x 6912, stride 36
    float* sm_qkv = sm + QKVOFF;   // per head 7168: q(64x36), k(64x36), v(64x40)
    float* sm_sc  = sm + WOFF;     // alias, per head 4352, stride 68

    const int b    = blockIdx.x;
    const int tid  = threadIdx.x;
    const int lane = tid & 31;
    const int warp = tid >> 5;
    const int g    = lane >> 2;
    const int tg   = lane & 3;
    // GEMM roles
    const int wm4 = warp >> 1;     // 0..3: 16-row block
    const int wn2 = warp & 1;      // 0..1: 96-col block = head-local
    // attention roles
    const int a_hl = warp >> 2;    // head-local 0/1
    const int a_q4 = warp & 3;     // 16-query-row block

    // ---- load X tile as tf32 ----
    const float* Xg = X + (size_t)b * (NTOK * DIM);
    #pragma unroll
    for (int it = 0; it < 16; it++) {
        const int f4 = tid + it * 256;
        const int r = f4 >> 6, c4 = (f4 & 63) * 4;
        float4 v = *(const float4*)(Xg + r * 256 + c4);
        float4 t;
        t.x = f2tf32(v.x); t.y = f2tf32(v.y); t.z = f2tf32(v.z); t.w = f2tf32(v.w);
        *(float4*)(sm_x + r * 260 + c4) = t;
    }

    // ---- weight load mapping (per thread: 6 float4 per 32-k chunk) ----
    // B rows [0,192): hl = row/96; within: [0,32)=Wq, [32,64)=Wk, [64,96)=Wv rows (h*32+d)
    const float* Wsrc[6];
    int dstoff[6];
    #pragma unroll
    for (int j = 0; j < 6; j++) {
        const int f4  = tid + j * 256;      // 0..1535
        const int row = f4 >> 3;
        const int c4  = (f4 & 7) * 4;
        const int hl  = row / 96;
        const int rem = row - hl * 96;
        const int t3  = rem >> 5;
        const int d   = rem & 31;
        const float* Wt = (t3 == 0) ? Wq : (t3 == 1) ? Wk : Wv;
        Wsrc[j]   = Wt + (size_t)(hl * 32 + d) * 256 + c4;
        dstoff[j] = row * 36 + c4;
    }

    // prefetch (hp=0, chunk=0)
    float4 wreg[6];
    #pragma unroll
    for (int j = 0; j < 6; j++) wreg[j] = *(const float4*)(Wsrc[j]);

    __syncthreads();   // X ready

    for (int hp = 0; hp < 4; hp++) {
        float acc[12][4];
        #pragma unroll
        for (int i = 0; i < 12; i++)
            #pragma unroll
            for (int j = 0; j < 4; j++) acc[i][j] = 0.f;

        #pragma unroll
        for (int kc = 0; kc < 8; kc++) {
            float* wb = sm_w + (kc & 1) * 6912;
            #pragma unroll
            for (int j = 0; j < 6; j++) {
                float4 t;
                t.x = f2tf32(wreg[j].x); t.y = f2tf32(wreg[j].y);
                t.z = f2tf32(wreg[j].z); t.w = f2tf32(wreg[j].w);
                *(float4*)(wb + dstoff[j]) = t;
            }
            __syncthreads();

            // prefetch next chunk (or next pair's chunk 0)
            if (kc < 7) {
                const size_t off = (size_t)hp * 64 * 256 + (kc + 1) * 32;
                #pragma unroll
                for (int j = 0; j < 6; j++) wreg[j] = *(const float4*)(Wsrc[j] + off);
            } else if (hp < 3) {
                const size_t off = (size_t)(hp + 1) * 64 * 256;
                #pragma unroll
                for (int j = 0; j < 6; j++) wreg[j] = *(const float4*)(Wsrc[j] + off);
            }

            // compute 4 k-steps on this chunk
            #pragma unroll
            for (int ks = 0; ks < 4; ks++) {
                const int xk = kc * 32 + ks * 8 + tg;
                const float* xrow = sm_x + (wm4 * 16 + g) * 260 + xk;
                uint32_t afr[4];
                afr[0] = fbits(xrow[0]);
                afr[1] = fbits(xrow[8 * 260]);
                afr[2] = fbits(xrow[4]);
                afr[3] = fbits(xrow[8 * 260 + 4]);
                #pragma unroll
                for (int nt = 0; nt < 12; nt++) {
                    const float* wrow = wb + (wn2 * 96 + nt * 8 + g) * 36 + ks * 8 + tg;
                    uint32_t bfr[2] = { fbits(wrow[0]), fbits(wrow[4]) };
                    mma8(acc[nt], afr, bfr);
                }
            }
        }

        // ---- epilogue: bias add, write Q/K/V tiles (tf32) ----
        {
            const int hloc = wn2;
            const int r0 = wm4 * 16 + g;
            #pragma unroll
            for (int nt = 0; nt < 12; nt++) {
                const int c0 = nt * 8 + tg * 2;
                const int t3 = nt >> 2;
                const int d  = c0 - t3 * 32;
                const float* Bt = (t3 == 0) ? Bq : (t3 == 1) ? Bk : Bv;
                const int bi = (hp * 2 + hloc) * 32 + d;
                const float b0 = Bt[bi], b1 = Bt[bi + 1];
                const int stride = (t3 < 2) ? 36 : 40;
                float* tile = sm_qkv + hloc * 7168 + ((t3 < 2) ? t3 * 2304 : 4608);
                tile[r0 * stride + d]           = f2tf32(acc[nt][0] + b0);
                tile[r0 * stride + d + 1]       = f2tf32(acc[nt][1] + b1);
                tile[(r0 + 8) * stride + d]     = f2tf32(acc[nt][2] + b0);
                tile[(r0 + 8) * stride + d + 1] = f2tf32(acc[nt][3] + b1);
            }
        }
        __syncthreads();

        // ================= attention for heads (hp*2, hp*2+1) =================
        const int h = hp * 2 + a_hl;
        const float* Qt = sm_qkv + a_hl * 7168;          // stride 36
        const float* Kt = Qt + 2304;                     // stride 36
        const float* Vt = Qt + 4608;                     // stride 40
        float* SCb = sm_sc + a_hl * 4352;                // stride 68

        // scores: warp rows [a_q4*16, +16) x 64
        float sacc[8][4];
        #pragma unroll
        for (int i = 0; i < 8; i++)
            #pragma unroll
            for (int j = 0; j < 4; j++) sacc[i][j] = 0.f;

        #pragma unroll
        for (int kc = 0; kc < HEADDIM; kc += 8) {
            const float* qrow = Qt + (a_q4 * 16 + g) * 36 + kc + tg;
            uint32_t afr[4];
            afr[0] = fbits(qrow[0]);
            afr[1] = fbits(qrow[8 * 36]);
            afr[2] = fbits(qrow[4]);
            afr[3] = fbits(qrow[8 * 36 + 4]);
            #pragma unroll
            for (int nt = 0; nt < 8; nt++) {
                const float* krow = Kt + (nt * 8 + g) * 36 + kc + tg;
                uint32_t bfr[2] = { fbits(krow[0]), fbits(krow[4]) };
                mma8(sacc[nt], afr, bfr);
            }
        }

        // scale + combined mask/bias -> scores smem (fp32)
        {
            const float scale = 0.17677669529663687f;    // 1/sqrt(32)
            const float* cmb = g_CMB + (((size_t)(b & (MASK_NW - 1)) * HEADS + h) * 4096);
            const int r0 = a_q4 * 16 + g;
            #pragma unroll
            for (int nt = 0; nt < 8; nt++) {
                const int c0 = nt * 8 + tg * 2;
                float2 m0v = *(const float2*)(cmb + r0 * 64 + c0);
                float2 m1v = *(const float2*)(cmb + (r0 + 8) * 64 + c0);
                SCb[r0 * 68 + c0]           = sacc[nt][0] * scale + m0v.x;
                SCb[r0 * 68 + c0 + 1]       = sacc[nt][1] * scale + m0v.y;
                SCb[(r0 + 8) * 68 + c0]     = sacc[nt][2] * scale + m1v.x;
                SCb[(r0 + 8) * 68 + c0 + 1] = sacc[nt][3] * scale + m1v.y;
            }
        }
        __syncwarp();

        // softmax over warp-owned rows; write P back as tf32
        #pragma unroll
        for (int rr = 0; rr < 16; rr++) {
            const int r = a_q4 * 16 + rr;
            float v0 = SCb[r * 68 + lane], v1 = SCb[r * 68 + lane + 32];
            float m = fmaxf(v0, v1);
            #pragma unroll
            for (int o = 16; o; o >>= 1) m = fmaxf(m, __shfl_xor_sync(0xffffffffu, m, o));
            float e0 = __expf(v0 - m), e1 = __expf(v1 - m);
            float s = e0 + e1;
            #pragma unroll
            for (int o = 16; o; o >>= 1) s += __shfl_xor_sync(0xffffffffu, s, o);
            const float inv = 1.0f / s;
            SCb[r * 68 + lane]      = f2tf32(e0 * inv);
            SCb[r * 68 + lane + 32] = f2tf32(e1 * inv);
        }
        __syncwarp();

        // PV: O[16 x 32] = P(16x64) @ V(64x32)
        float oacc[4][4];
        #pragma unroll
        for (int i = 0; i < 4; i++)
            #pragma unroll
            for (int j = 0; j < 4; j++) oacc[i][j] = 0.f;

        #pragma unroll
        for (int kc = 0; kc < NTOK; kc += 8) {
            const float* prow = SCb + (a_q4 * 16 + g) * 68 + kc + tg;
            uint32_t afr[4];
            afr[0] = fbits(prow[0]);
            afr[1] = fbits(prow[8 * 68]);
            afr[2] = fbits(prow[4]);
            afr[3] = fbits(prow[8 * 68 + 4]);
            #pragma unroll
            for (int nt = 0; nt < 4; nt++) {
                uint32_t bfr[2];
                bfr[0] = fbits(Vt[(kc + tg) * 40 + nt * 8 + g]);
                bfr[1] = fbits(Vt[(kc + tg + 4) * 40 + nt * 8 + g]);
                mma8(oacc[nt], afr, bfr);
            }
        }

        // write output
        {
            float* ob = out + (size_t)b * (NTOK * DIM) + h * HEADDIM;
            const int r0 = a_q4 * 16 + g;
            #pragma unroll
            for (int nt = 0; nt < 4; nt++) {
                const int c0 = nt * 8 + tg * 2;
                *(float2*)(ob + (size_t)r0 * DIM + c0)       = make_float2(oacc[nt][0], oacc[nt][1]);
                *(float2*)(ob + (size_t)(r0 + 8) * DIM + c0) = make_float2(oacc[nt][2], oacc[nt][3]);
            }
        }
        __syncthreads();   // protect sc (aliases W bufs) before next pair's STS
    }
}

// ---------------------------------------------------------------------------
extern "C" void kernel_launch(void* const* d_in, const int* in_sizes, int n_in,
                              void* d_out, int out_size)
{
    const float* hs   = (const float*)d_in[0];
    const float* mask = (const float*)d_in[1];
    const float* wq   = (const float*)d_in[2];
    const float* bq   = (const float*)d_in[3];
    const float* wk   = (const float*)d_in[4];
    const float* bk   = (const float*)d_in[5];
    const float* wv   = (const float*)d_in[6];
    const float* bv   = (const float*)d_in[7];
    const float* bt   = (const float*)d_in[8];
    const int*   ri   = (const int*)d_in[9];
    float* out = (float*)d_out;

    static bool attr_set = false;
    if (!attr_set) {
        cudaFuncSetAttribute(fused_qkv_attn,
                             cudaFuncAttributeMaxDynamicSharedMemorySize,
                             SMEM_FLOATS * 4);
        attr_set = true;
    }

    prep_cmb<<<(MASK_NW * HEADS * NTOK * NTOK) / 256, 256>>>(mask, bt, ri);
    fused_qkv_attn<<<BATCH, 256, SMEM_FLOATS * 4>>>(hs, wq, bq, wk, bk, wv, bv, out);
}

// round 4
// speedup vs baseline: 1.0720x; 1.0720x over previous
#include <cuda_runtime.h>
#include <cstdint>

#define BATCH   2048
#define NTOK    64
#define DIM     256
#define HEADS   8
#define HEADDIM 32
#define MASK_NW 64

// Scratch: Q, K, V [B*N, DIM]; CMB = mask + gathered relative bias [w][h][64*64]
__device__ float g_Q[(size_t)BATCH * NTOK * DIM];
__device__ float g_K[(size_t)BATCH * NTOK * DIM];
__device__ float g_V[(size_t)BATCH * NTOK * DIM];
__device__ float g_CMB[(size_t)MASK_NW * HEADS * NTOK * NTOK];

__device__ __forceinline__ float f2tf32(float x) {
    float r;
    asm("cvt.rna.tf32.f32 %0, %1;" : "=f"(r) : "f"(x));
    return r;
}
__device__ __forceinline__ uint32_t fbits(float x) { return __float_as_uint(x); }

__device__ __forceinline__ void mma8(float* d, const uint32_t* a, const uint32_t* b) {
    asm("mma.sync.aligned.m16n8k8.row.col.f32.tf32.tf32.f32 "
        "{%0,%1,%2,%3}, {%4,%5,%6,%7}, {%8,%9}, {%0,%1,%2,%3};"
        : "+f"(d[0]), "+f"(d[1]), "+f"(d[2]), "+f"(d[3])
        : "r"(a[0]), "r"(a[1]), "r"(a[2]), "r"(a[3]), "r"(b[0]), "r"(b[1]));
}

// ---------------------------------------------------------------------------
// Kernel 0: precompute combined mask + relative-position bias.
// ---------------------------------------------------------------------------
__global__ void prep_cmb(const float* __restrict__ mask,
                         const float* __restrict__ bt,
                         const int*   __restrict__ ri)
{
    const int idx = blockIdx.x * 256 + threadIdx.x;
    const int p = idx & 4095;
    const int h = (idx >> 12) & 7;
    const int w = idx >> 15;
    g_CMB[idx] = mask[w * 4096 + p] + bt[ri[p] * 8 + h];
}

// ---------------------------------------------------------------------------
// Kernel 1: fused QKV projection GEMM via tf32 mma.sync. (R1 design, verified)
// ---------------------------------------------------------------------------
__global__ __launch_bounds__(256) void qkv_gemm_tc(
    const float* __restrict__ X,
    const float* __restrict__ Wq, const float* __restrict__ Bq,
    const float* __restrict__ Wk, const float* __restrict__ Bk,
    const float* __restrict__ Wv, const float* __restrict__ Bv)
{
    constexpr int BK = 32;
    constexpr int KTILES = DIM / BK;   // 8

    __shared__ float As[128][36];
    __shared__ float Bs[128][36];

    const int tid  = threadIdx.x;
    const int m0   = blockIdx.y * 128;
    const int nsel = blockIdx.x;       // 0..5

    const float* W; const float* bias; float* outp;
    if (nsel < 2)      { W = Wq; bias = Bq; outp = g_Q; }
    else if (nsel < 4) { W = Wk; bias = Bk; outp = g_K; }
    else               { W = Wv; bias = Bv; outp = g_V; }
    const int nl0 = (nsel & 1) * 128;

    const int lane = tid & 31;
    const int warp = tid >> 5;
    const int g  = lane >> 2;
    const int tg = lane & 3;
    const int wm = (warp >> 1) * 32;
    const int wn = (warp & 1) * 64;

    const int lrow = tid >> 1;
    const int lq   = (tid & 1) * 16;

    float acc[2][8][4] = {};

    float4 va[4], vb[4];
    {
        const float* xa = X + (size_t)(m0 + lrow) * DIM + lq;
        const float* xb = W + (size_t)(nl0 + lrow) * DIM + lq;
        #pragma unroll
        for (int i = 0; i < 4; i++) {
            va[i] = *(const float4*)(xa + i * 4);
            vb[i] = *(const float4*)(xb + i * 4);
        }
    }

    for (int kt = 0; kt < KTILES; kt++) {
        #pragma unroll
        for (int i = 0; i < 4; i++) {
            const int c = lq + i * 4;
            As[lrow][c + 0] = f2tf32(va[i].x);
            As[lrow][c + 1] = f2tf32(va[i].y);
            As[lrow][c + 2] = f2tf32(va[i].z);
            As[lrow][c + 3] = f2tf32(va[i].w);
            Bs[lrow][c + 0] = f2tf32(vb[i].x);
            Bs[lrow][c + 1] = f2tf32(vb[i].y);
            Bs[lrow][c + 2] = f2tf32(vb[i].z);
            Bs[lrow][c + 3] = f2tf32(vb[i].w);
        }
        __syncthreads();

        if (kt + 1 < KTILES) {
            const float* xa = X + (size_t)(m0 + lrow) * DIM + (kt + 1) * BK + lq;
            const float* xb = W + (size_t)(nl0 + lrow) * DIM + (kt + 1) * BK + lq;
            #pragma unroll
            for (int i = 0; i < 4; i++) {
                va[i] = *(const float4*)(xa + i * 4);
                vb[i] = *(const float4*)(xb + i * 4);
            }
        }

        #pragma unroll
        for (int kc = 0; kc < BK; kc += 8) {
            uint32_t afr[2][4];
            #pragma unroll
            for (int mt = 0; mt < 2; mt++) {
                const int r = wm + mt * 16;
                afr[mt][0] = fbits(As[r + g    ][kc + tg]);
                afr[mt][1] = fbits(As[r + g + 8][kc + tg]);
                afr[mt][2] = fbits(As[r + g    ][kc + tg + 4]);
                afr[mt][3] = fbits(As[r + g + 8][kc + tg + 4]);
            }
            uint32_t bfr[8][2];
            #pragma unroll
            for (int nt = 0; nt < 8; nt++) {
                const int c = wn + nt * 8;
                bfr[nt][0] = fbits(Bs[c + g][kc + tg]);
                bfr[nt][1] = fbits(Bs[c + g][kc + tg + 4]);
            }
            #pragma unroll
            for (int mt = 0; mt < 2; mt++)
                #pragma unroll
                for (int nt = 0; nt < 8; nt++)
                    mma8(acc[mt][nt], afr[mt], bfr[nt]);
        }
        __syncthreads();
    }

    #pragma unroll
    for (int nt = 0; nt < 8; nt++) {
        const int c = nl0 + wn + nt * 8 + tg * 2;
        const float b0 = bias[c], b1 = bias[c + 1];
        #pragma unroll
        for (int mt = 0; mt < 2; mt++) {
            const int r = m0 + wm + mt * 16 + g;
            *(float2*)(outp + (size_t)r * DIM + c)       = make_float2(acc[mt][nt][0] + b0, acc[mt][nt][1] + b1);
            *(float2*)(outp + (size_t)(r + 8) * DIM + c) = make_float2(acc[mt][nt][2] + b0, acc[mt][nt][3] + b1);
        }
    }
}

// ---------------------------------------------------------------------------
// Kernel 2: attention, fragment-packed smem + register softmax.
// CTA = (window, head), 128 threads / 4 warps; warp w owns rows [16w,16w+16).
//
// Packed layouts (tf32 data):
//  qp[mtile4][ktile4][lane32][4]  A-frags: slots (rowg,k tg),(g+8,tg),(g,tg+4),(g+8,tg+4)
//  kp[kc4][nt8][lane32][2]        B-frags for scores: (k=tg,n=g),(k=tg+4,n=g)
//  vp[kc8][nt4][lane32][2]        B-frags for PV
// ---------------------------------------------------------------------------
__global__ __launch_bounds__(128) void attn_tc(float* __restrict__ out)
{
    __shared__ float qp[2048];
    __shared__ float kp[2048];
    __shared__ float vp[2048];

    const int b = blockIdx.x;
    const int h = blockIdx.y;
    const int tid  = threadIdx.x;
    const int lane = tid & 31;
    const int warp = tid >> 5;
    const int g  = lane >> 2;
    const int tg = lane & 3;

    // ---- cooperative load + fragment packing ----
    const size_t gbase = (size_t)b * (NTOK * DIM) + (size_t)h * HEADDIM;
    {
        const int r  = tid >> 1;            // token row 0..63
        const int ch = (tid & 1) * 16;      // col half 0 or 16
        const size_t rowoff = gbase + (size_t)r * DIM;

        // per-row constants
        const int q_mt = r >> 4, q_g = r & 7, q_hi = (r >> 3) & 1;
        const int k_nt = r >> 3, k_g = r & 7;
        const int v_kc = r >> 3, v_tg = r & 3, v_sl = (r >> 2) & 1;

        #pragma unroll
        for (int it = 0; it < 4; it++) {
            const int d0 = ch + it * 4;
            const float4 q4 = *(const float4*)(g_Q + rowoff + d0);
            const float4 k4 = *(const float4*)(g_K + rowoff + d0);
            const float4 v4 = *(const float4*)(g_V + rowoff + d0);

            // Q -> A-frag pack
            {
                const int kt  = d0 >> 3;
                const int sl  = q_hi + 2 * ((d0 >> 2) & 1);
                float* dst = qp + (q_mt * 4 + kt) * 128 + q_g * 16 + sl;
                dst[0]  = f2tf32(q4.x); dst[4]  = f2tf32(q4.y);
                dst[8]  = f2tf32(q4.z); dst[12] = f2tf32(q4.w);
            }
            // K -> B-frag pack (scores)
            {
                const int kc = d0 >> 3;
                const int sl = (d0 >> 2) & 1;
                float* dst = kp + (kc * 8 + k_nt) * 64 + k_g * 8 + sl;
                dst[0] = f2tf32(k4.x); dst[2] = f2tf32(k4.y);
                dst[4] = f2tf32(k4.z); dst[6] = f2tf32(k4.w);
            }
            // V -> B-frag pack (PV)
            {
                const int nt  = d0 >> 3;
                const int gv0 = d0 & 7;
                float* dst = vp + (v_kc * 4 + nt) * 64 + gv0 * 8 + v_tg * 2 + v_sl;
                dst[0]  = f2tf32(v4.x); dst[8]  = f2tf32(v4.y);
                dst[16] = f2tf32(v4.z); dst[24] = f2tf32(v4.w);
            }
        }
    }
    __syncthreads();

    // ---- scores: S = Q K^T  (warp rows [16*warp, +16) x 64 cols) ----
    float sacc[8][4];
    #pragma unroll
    for (int i = 0; i < 8; i++)
        #pragma unroll
        for (int j = 0; j < 4; j++) sacc[i][j] = 0.f;

    #pragma unroll
    for (int kc = 0; kc < 4; kc++) {
        const float4 a4 = *(const float4*)(qp + (warp * 4 + kc) * 128 + lane * 4);
        uint32_t afr[4] = { fbits(a4.x), fbits(a4.y), fbits(a4.z), fbits(a4.w) };
        #pragma unroll
        for (int nt = 0; nt < 8; nt++) {
            const float2 b2 = *(const float2*)(kp + (kc * 8 + nt) * 64 + lane * 2);
            uint32_t bfr[2] = { fbits(b2.x), fbits(b2.y) };
            mma8(sacc[nt], afr, bfr);
        }
    }

    // ---- scale + mask/bias into registers ----
    const float scale = 0.17677669529663687f;   // 1/sqrt(32)
    const float* cmb = g_CMB + (((size_t)(b & (MASK_NW - 1)) * HEADS + h) << 12);
    const int r0 = warp * 16 + g;

    float v0[16], v1[16];   // row r0 / row r0+8: cols nt*8 + tg*2 + {0,1}
    #pragma unroll
    for (int nt = 0; nt < 8; nt++) {
        const int c0 = nt * 8 + tg * 2;
        const float2 m0v = *(const float2*)(cmb + r0 * 64 + c0);
        const float2 m1v = *(const float2*)(cmb + (r0 + 8) * 64 + c0);
        v0[nt * 2]     = sacc[nt][0] * scale + m0v.x;
        v0[nt * 2 + 1] = sacc[nt][1] * scale + m0v.y;
        v1[nt * 2]     = sacc[nt][2] * scale + m1v.x;
        v1[nt * 2 + 1] = sacc[nt][3] * scale + m1v.y;
    }

    // ---- register softmax (row spread over the 4 lanes of a g-group) ----
    {
        float mx0 = v0[0], mx1 = v1[0];
        #pragma unroll
        for (int i = 1; i < 16; i++) { mx0 = fmaxf(mx0, v0[i]); mx1 = fmaxf(mx1, v1[i]); }
        mx0 = fmaxf(mx0, __shfl_xor_sync(0xffffffffu, mx0, 1));
        mx0 = fmaxf(mx0, __shfl_xor_sync(0xffffffffu, mx0, 2));
        mx1 = fmaxf(mx1, __shfl_xor_sync(0xffffffffu, mx1, 1));
        mx1 = fmaxf(mx1, __shfl_xor_sync(0xffffffffu, mx1, 2));

        float s0 = 0.f, s1 = 0.f;
        #pragma unroll
        for (int i = 0; i < 16; i++) {
            v0[i] = __expf(v0[i] - mx0); s0 += v0[i];
            v1[i] = __expf(v1[i] - mx1); s1 += v1[i];
        }
        s0 += __shfl_xor_sync(0xffffffffu, s0, 1);
        s0 += __shfl_xor_sync(0xffffffffu, s0, 2);
        s1 += __shfl_xor_sync(0xffffffffu, s1, 1);
        s1 += __shfl_xor_sync(0xffffffffu, s1, 2);
        const float inv0 = 1.0f / s0, inv1 = 1.0f / s1;
        #pragma unroll
        for (int i = 0; i < 16; i++) {
            v0[i] = f2tf32(v0[i] * inv0);
            v1[i] = f2tf32(v1[i] * inv1);
        }
    }

    // ---- PV with shuffle C->A fragment transpose ----
    float oacc[4][4];
    #pragma unroll
    for (int i = 0; i < 4; i++)
        #pragma unroll
        for (int j = 0; j < 4; j++) oacc[i][j] = 0.f;

    const int srcA = (lane & 28) | (tg >> 1);
    const int srcB = srcA | 2;
    const bool odd = tg & 1;

    #pragma unroll
    for (int kt = 0; kt < 8; kt++) {
        const float x0 = __shfl_sync(0xffffffffu, v0[kt * 2],     srcA);
        const float x1 = __shfl_sync(0xffffffffu, v0[kt * 2 + 1], srcA);
        const float y0 = __shfl_sync(0xffffffffu, v0[kt * 2],     srcB);
        const float y1 = __shfl_sync(0xffffffffu, v0[kt * 2 + 1], srcB);
        const float z0 = __shfl_sync(0xffffffffu, v1[kt * 2],     srcA);
        const float z1 = __shfl_sync(0xffffffffu, v1[kt * 2 + 1], srcA);
        const float w0 = __shfl_sync(0xffffffffu, v1[kt * 2],     srcB);
        const float w1 = __shfl_sync(0xffffffffu, v1[kt * 2 + 1], srcB);
        uint32_t afr[4];
        afr[0] = fbits(odd ? x1 : x0);   // (row g,   k kt*8+tg)
        afr[1] = fbits(odd ? z1 : z0);   // (row g+8, k kt*8+tg)
        afr[2] = fbits(odd ? y1 : y0);   // (row g,   k kt*8+tg+4)
        afr[3] = fbits(odd ? w1 : w0);   // (row g+8, k kt*8+tg+4)
        #pragma unroll
        for (int nt = 0; nt < 4; nt++) {
            const float2 b2 = *(const float2*)(vp + (kt * 4 + nt) * 64 + lane * 2);
            uint32_t bfr[2] = { fbits(b2.x), fbits(b2.y) };
            mma8(oacc[nt], afr, bfr);
        }
    }

    // ---- output ----
    {
        float* ob = out + gbase;
        #pragma unroll
        for (int nt = 0; nt < 4; nt++) {
            const int c0 = nt * 8 + tg * 2;
            *(float2*)(ob + (size_t)r0 * DIM + c0)       = make_float2(oacc[nt][0], oacc[nt][1]);
            *(float2*)(ob + (size_t)(r0 + 8) * DIM + c0) = make_float2(oacc[nt][2], oacc[nt][3]);
        }
    }
}

// ---------------------------------------------------------------------------
extern "C" void kernel_launch(void* const* d_in, const int* in_sizes, int n_in,
                              void* d_out, int out_size)
{
    const float* hs   = (const float*)d_in[0];
    const float* mask = (const float*)d_in[1];
    const float* wq   = (const float*)d_in[2];
    const float* bq   = (const float*)d_in[3];
    const float* wk   = (const float*)d_in[4];
    const float* bk   = (const float*)d_in[5];
    const float* wv   = (const float*)d_in[6];
    const float* bv   = (const float*)d_in[7];
    const float* bt   = (const float*)d_in[8];
    const int*   ri   = (const int*)d_in[9];
    float* out = (float*)d_out;

    prep_cmb<<<(MASK_NW * HEADS * NTOK * NTOK) / 256, 256>>>(mask, bt, ri);

    dim3 gemm_grid(6, (BATCH * NTOK) / 128);
    qkv_gemm_tc<<<gemm_grid, 256>>>(hs, wq, bq, wk, bk, wv, bv);

    dim3 attn_grid(BATCH, HEADS);
    attn_tc<<<attn_grid, 128>>>(out);
}

// round 6
// speedup vs baseline: 1.5700x; 1.4645x over previous
#include <cuda_runtime.h>
#include <cuda_fp16.h>
#include <cstdint>

#define BATCH   2048
#define NTOK    64
#define DIM     256
#define HEADS   8
#define HEADDIM 32
#define MASK_NW 64

// Scratch: Q, K, V [B*N, DIM] in fp16; CMB = mask + gathered rel bias (fp32)
__device__ __half g_Q[(size_t)BATCH * NTOK * DIM];
__device__ __half g_K[(size_t)BATCH * NTOK * DIM];
__device__ __half g_V[(size_t)BATCH * NTOK * DIM];
__device__ float  g_CMB[(size_t)MASK_NW * HEADS * NTOK * NTOK];

__device__ __forceinline__ uint32_t h2bits(float a, float b) {
    __half2 h = __floats2half2_rn(a, b);
    return *(uint32_t*)&h;
}
__device__ __forceinline__ uint32_t lds_h2(const __half* p) {
    return *(const uint32_t*)p;
}

__device__ __forceinline__ void mma16(float* d, const uint32_t* a, const uint32_t* b) {
    asm("mma.sync.aligned.m16n8k16.row.col.f32.f16.f16.f32 "
        "{%0,%1,%2,%3}, {%4,%5,%6,%7}, {%8,%9}, {%0,%1,%2,%3};"
        : "+f"(d[0]), "+f"(d[1]), "+f"(d[2]), "+f"(d[3])
        : "r"(a[0]), "r"(a[1]), "r"(a[2]), "r"(a[3]), "r"(b[0]), "r"(b[1]));
}

// ---------------------------------------------------------------------------
// Kernel 0: precompute combined mask + relative-position bias.
// ---------------------------------------------------------------------------
__global__ void prep_cmb(const float* __restrict__ mask,
                         const float* __restrict__ bt,
                         const int*   __restrict__ ri)
{
    const int idx = blockIdx.x * 256 + threadIdx.x;
    const int p = idx & 4095;
    const int h = (idx >> 12) & 7;
    const int w = idx >> 15;
    g_CMB[idx] = mask[w * 4096 + p] + bt[ri[p] * 8 + h];
}

// ---------------------------------------------------------------------------
// Kernel 1: fused QKV projection GEMM via fp16 mma (fp32 accumulate).
//   out[m, n] = sum_k X[m,k] * W[n,k] + bias[n]   -> __half scratch
//   CTA tile 128x128x32, 8 warps, warp tile 32x64, m16n8k16.
// ---------------------------------------------------------------------------
__global__ __launch_bounds__(256) void qkv_gemm_tc(
    const float* __restrict__ X,
    const float* __restrict__ Wq, const float* __restrict__ Bq,
    const float* __restrict__ Wk, const float* __restrict__ Bk,
    const float* __restrict__ Wv, const float* __restrict__ Bv)
{
    constexpr int BK = 32;
    constexpr int KTILES = DIM / BK;   // 8

    __shared__ __half As[128][40];
    __shared__ __half Bs[128][40];

    const int tid  = threadIdx.x;
    const int m0   = blockIdx.y * 128;
    const int nsel = blockIdx.x;       // 0..5

    const float* W; const float* bias; __half* outp;
    if (nsel < 2)      { W = Wq; bias = Bq; outp = g_Q; }
    else if (nsel < 4) { W = Wk; bias = Bk; outp = g_K; }
    else               { W = Wv; bias = Bv; outp = g_V; }
    const int nl0 = (nsel & 1) * 128;

    const int lane = tid & 31;
    const int warp = tid >> 5;
    const int g  = lane >> 2;
    const int tg = lane & 3;
    const int wm = (warp >> 1) * 32;
    const int wn = (warp & 1) * 64;

    const int lrow = tid >> 1;
    const int lq   = (tid & 1) * 16;

    float acc[2][8][4] = {};

    float4 va[4], vb[4];
    {
        const float* xa = X + (size_t)(m0 + lrow) * DIM + lq;
        const float* xb = W + (size_t)(nl0 + lrow) * DIM + lq;
        #pragma unroll
        for (int i = 0; i < 4; i++) {
            va[i] = *(const float4*)(xa + i * 4);
            vb[i] = *(const float4*)(xb + i * 4);
        }
    }

    for (int kt = 0; kt < KTILES; kt++) {
        #pragma unroll
        for (int i = 0; i < 4; i++) {
            const int c = lq + i * 4;
            *(uint32_t*)&As[lrow][c]     = h2bits(va[i].x, va[i].y);
            *(uint32_t*)&As[lrow][c + 2] = h2bits(va[i].z, va[i].w);
            *(uint32_t*)&Bs[lrow][c]     = h2bits(vb[i].x, vb[i].y);
            *(uint32_t*)&Bs[lrow][c + 2] = h2bits(vb[i].z, vb[i].w);
        }
        __syncthreads();

        if (kt + 1 < KTILES) {
            const float* xa = X + (size_t)(m0 + lrow) * DIM + (kt + 1) * BK + lq;
            const float* xb = W + (size_t)(nl0 + lrow) * DIM + (kt + 1) * BK + lq;
            #pragma unroll
            for (int i = 0; i < 4; i++) {
                va[i] = *(const float4*)(xa + i * 4);
                vb[i] = *(const float4*)(xb + i * 4);
            }
        }

        #pragma unroll
        for (int kc = 0; kc < BK; kc += 16) {
            uint32_t afr[2][4];
            #pragma unroll
            for (int mt = 0; mt < 2; mt++) {
                const int r = wm + mt * 16;
                afr[mt][0] = lds_h2(&As[r + g    ][kc + 2 * tg]);
                afr[mt][1] = lds_h2(&As[r + g + 8][kc + 2 * tg]);
                afr[mt][2] = lds_h2(&As[r + g    ][kc + 2 * tg + 8]);
                afr[mt][3] = lds_h2(&As[r + g + 8][kc + 2 * tg + 8]);
            }
            uint32_t bfr[8][2];
            #pragma unroll
            for (int nt = 0; nt < 8; nt++) {
                const int c = wn + nt * 8;
                bfr[nt][0] = lds_h2(&Bs[c + g][kc + 2 * tg]);
                bfr[nt][1] = lds_h2(&Bs[c + g][kc + 2 * tg + 8]);
            }
            #pragma unroll
            for (int mt = 0; mt < 2; mt++)
                #pragma unroll
                for (int nt = 0; nt < 8; nt++)
                    mma16(acc[mt][nt], afr[mt], bfr[nt]);
        }
        __syncthreads();
    }

    // epilogue: bias add in fp32, store half2
    #pragma unroll
    for (int nt = 0; nt < 8; nt++) {
        const int c = nl0 + wn + nt * 8 + tg * 2;
        const float b0 = bias[c], b1 = bias[c + 1];
        #pragma unroll
        for (int mt = 0; mt < 2; mt++) {
            const int r = m0 + wm + mt * 16 + g;
            *(uint32_t*)(outp + (size_t)r * DIM + c)       = h2bits(acc[mt][nt][0] + b0, acc[mt][nt][1] + b1);
            *(uint32_t*)(outp + (size_t)(r + 8) * DIM + c) = h2bits(acc[mt][nt][2] + b0, acc[mt][nt][3] + b1);
        }
    }
}

// ---------------------------------------------------------------------------
// Kernel 2: fp16 attention, CTA = (window, head), 128 threads / 4 warps.
// Warp w owns query rows [16w, 16w+16). P: C-frag -> A-frag by register pack.
//  qs, ks : [64][40] halves (row = token, col = head dim)
//  vt     : [32][72] halves (row = head dim, col = token)  -- transposed
// ---------------------------------------------------------------------------
__global__ __launch_bounds__(128) void attn_tc(float* __restrict__ out)
{
    __shared__ __half qs[64 * 40];
    __shared__ __half ks[64 * 40];
    __shared__ __half vt[32 * 72];

    const int b = blockIdx.x;
    const int h = blockIdx.y;
    const int tid  = threadIdx.x;
    const int lane = tid & 31;
    const int warp = tid >> 5;
    const int g  = lane >> 2;
    const int tg = lane & 3;

    // ---- cooperative load: thread = (token row, 16-col half) ----
    const size_t gbase = (size_t)b * (NTOK * DIM) + (size_t)h * HEADDIM;
    {
        const int r  = tid >> 1;
        const int ch = (tid & 1) * 16;
        const size_t go = gbase + (size_t)r * DIM + ch;

        uint4 q0 = *(const uint4*)(g_Q + go);
        uint4 q1 = *(const uint4*)(g_Q + go + 8);
        uint4 k0 = *(const uint4*)(g_K + go);
        uint4 k1 = *(const uint4*)(g_K + go + 8);
        uint4 v0q = *(const uint4*)(g_V + go);
        uint4 v1q = *(const uint4*)(g_V + go + 8);

        *(uint4*)&qs[r * 40 + ch]     = q0;
        *(uint4*)&qs[r * 40 + ch + 8] = q1;
        *(uint4*)&ks[r * 40 + ch]     = k0;
        *(uint4*)&ks[r * 40 + ch + 8] = k1;

        // V transpose: vt[d][r] = V[r][d]
        const __half* vh = (const __half*)&v0q;
        #pragma unroll
        for (int j = 0; j < 8; j++) vt[(ch + j) * 72 + r] = vh[j];
        vh = (const __half*)&v1q;
        #pragma unroll
        for (int j = 0; j < 8; j++) vt[(ch + 8 + j) * 72 + r] = vh[j];
    }
    __syncthreads();

    // ---- scores: S = Q K^T (warp rows [16w,+16) x 64 cols), k = 32 = 2 tiles
    float sacc[8][4];
    #pragma unroll
    for (int i = 0; i < 8; i++)
        #pragma unroll
        for (int j = 0; j < 4; j++) sacc[i][j] = 0.f;

    const int r0 = warp * 16 + g;
    #pragma unroll
    for (int kc = 0; kc < HEADDIM; kc += 16) {
        uint32_t afr[4];
        afr[0] = lds_h2(&qs[(warp * 16 + g)     * 40 + kc + 2 * tg]);
        afr[1] = lds_h2(&qs[(warp * 16 + g + 8) * 40 + kc + 2 * tg]);
        afr[2] = lds_h2(&qs[(warp * 16 + g)     * 40 + kc + 2 * tg + 8]);
        afr[3] = lds_h2(&qs[(warp * 16 + g + 8) * 40 + kc + 2 * tg + 8]);
        #pragma unroll
        for (int nt = 0; nt < 8; nt++) {
            uint32_t bfr[2];
            bfr[0] = lds_h2(&ks[(nt * 8 + g) * 40 + kc + 2 * tg]);
            bfr[1] = lds_h2(&ks[(nt * 8 + g) * 40 + kc + 2 * tg + 8]);
            mma16(sacc[nt], afr, bfr);
        }
    }

    // ---- scale + mask/bias into registers ----
    const float scale = 0.17677669529663687f;   // 1/sqrt(32)
    const float* cmb = g_CMB + (((size_t)(b & (MASK_NW - 1)) * HEADS + h) << 12);

    float v0[16], v1[16];   // rows r0 / r0+8, cols nt*8 + 2tg + {0,1}
    #pragma unroll
    for (int nt = 0; nt < 8; nt++) {
        const int c0 = nt * 8 + tg * 2;
        const float2 m0v = *(const float2*)(cmb + r0 * 64 + c0);
        const float2 m1v = *(const float2*)(cmb + (r0 + 8) * 64 + c0);
        v0[nt * 2]     = sacc[nt][0] * scale + m0v.x;
        v0[nt * 2 + 1] = sacc[nt][1] * scale + m0v.y;
        v1[nt * 2]     = sacc[nt][2] * scale + m1v.x;
        v1[nt * 2 + 1] = sacc[nt][3] * scale + m1v.y;
    }

    // ---- register softmax (row spread over 4 tg lanes) ----
    {
        float mx0 = v0[0], mx1 = v1[0];
        #pragma unroll
        for (int i = 1; i < 16; i++) { mx0 = fmaxf(mx0, v0[i]); mx1 = fmaxf(mx1, v1[i]); }
        mx0 = fmaxf(mx0, __shfl_xor_sync(0xffffffffu, mx0, 1));
        mx0 = fmaxf(mx0, __shfl_xor_sync(0xffffffffu, mx0, 2));
        mx1 = fmaxf(mx1, __shfl_xor_sync(0xffffffffu, mx1, 1));
        mx1 = fmaxf(mx1, __shfl_xor_sync(0xffffffffu, mx1, 2));

        float s0 = 0.f, s1 = 0.f;
        #pragma unroll
        for (int i = 0; i < 16; i++) {
            v0[i] = __expf(v0[i] - mx0); s0 += v0[i];
            v1[i] = __expf(v1[i] - mx1); s1 += v1[i];
        }
        s0 += __shfl_xor_sync(0xffffffffu, s0, 1);
        s0 += __shfl_xor_sync(0xffffffffu, s0, 2);
        s1 += __shfl_xor_sync(0xffffffffu, s1, 1);
        s1 += __shfl_xor_sync(0xffffffffu, s1, 2);
        const float inv0 = 1.0f / s0, inv1 = 1.0f / s1;
        #pragma unroll
        for (int i = 0; i < 16; i++) { v0[i] *= inv0; v1[i] *= inv1; }
    }

    // ---- PV: O[16x32] = P(16x64) @ V(64x32); P C-frags -> A-frags by packing
    float oacc[4][4];
    #pragma unroll
    for (int i = 0; i < 4; i++)
        #pragma unroll
        for (int j = 0; j < 4; j++) oacc[i][j] = 0.f;

    #pragma unroll
    for (int kt = 0; kt < 4; kt++) {
        uint32_t afr[4];
        afr[0] = h2bits(v0[4 * kt],     v0[4 * kt + 1]);   // (g,   klo pair)
        afr[1] = h2bits(v1[4 * kt],     v1[4 * kt + 1]);   // (g+8, klo pair)
        afr[2] = h2bits(v0[4 * kt + 2], v0[4 * kt + 3]);   // (g,   khi pair)
        afr[3] = h2bits(v1[4 * kt + 2], v1[4 * kt + 3]);   // (g+8, khi pair)
        #pragma unroll
        for (int nt = 0; nt < 4; nt++) {
            uint32_t bfr[2];
            bfr[0] = lds_h2(&vt[(nt * 8 + g) * 72 + kt * 16 + 2 * tg]);
            bfr[1] = lds_h2(&vt[(nt * 8 + g) * 72 + kt * 16 + 2 * tg + 8]);
            mma16(oacc[nt], afr, bfr);
        }
    }

    // ---- output (fp32) ----
    {
        float* ob = out + gbase;
        #pragma unroll
        for (int nt = 0; nt < 4; nt++) {
            const int c0 = nt * 8 + tg * 2;
            *(float2*)(ob + (size_t)r0 * DIM + c0)       = make_float2(oacc[nt][0], oacc[nt][1]);
            *(float2*)(ob + (size_t)(r0 + 8) * DIM + c0) = make_float2(oacc[nt][2], oacc[nt][3]);
        }
    }
}

// ---------------------------------------------------------------------------
extern "C" void kernel_launch(void* const* d_in, const int* in_sizes, int n_in,
                              void* d_out, int out_size)
{
    const float* hs   = (const float*)d_in[0];
    const float* mask = (const float*)d_in[1];
    const float* wq   = (const float*)d_in[2];
    const float* bq   = (const float*)d_in[3];
    const float* wk   = (const float*)d_in[4];
    const float* bk   = (const float*)d_in[5];
    const float* wv   = (const float*)d_in[6];
    const float* bv   = (const float*)d_in[7];
    const float* bt   = (const float*)d_in[8];
    const int*   ri   = (const int*)d_in[9];
    float* out = (float*)d_out;

    prep_cmb<<<(MASK_NW * HEADS * NTOK * NTOK) / 256, 256>>>(mask, bt, ri);

    dim3 gemm_grid(6, (BATCH * NTOK) / 128);
    qkv_gemm_tc<<<gemm_grid, 256>>>(hs, wq, bq, wk, bk, wv, bv);

    dim3 attn_grid(BATCH, HEADS);
    attn_tc<<<attn_grid, 128>>>(out);
}

// round 7
// speedup vs baseline: 1.7789x; 1.1330x over previous
#include <cuda_runtime.h>
#include <cuda_fp16.h>
#include <cstdint>

#define BATCH   2048
#define NTOK    64
#define DIM     256
#define HEADS   8
#define HEADDIM 32
#define MASK_NW 64

// fp16 staging: X, W (q|k|v), scratch Q/K/V; CMB fp32
__device__ __half g_Xh[(size_t)BATCH * NTOK * DIM];
__device__ __half g_Wh[3 * DIM * DIM];
__device__ __half g_Q[(size_t)BATCH * NTOK * DIM];
__device__ __half g_K[(size_t)BATCH * NTOK * DIM];
__device__ __half g_V[(size_t)BATCH * NTOK * DIM];
__device__ float  g_CMB[(size_t)MASK_NW * HEADS * NTOK * NTOK];

__device__ __forceinline__ uint32_t h2bits(float a, float b) {
    __half2 h = __floats2half2_rn(a, b);
    return *(uint32_t*)&h;
}
__device__ __forceinline__ uint32_t smem_u32(const void* p) {
    return (uint32_t)__cvta_generic_to_shared(p);
}
__device__ __forceinline__ void ldsm_x4(uint32_t* r, uint32_t a) {
    asm volatile("ldmatrix.sync.aligned.m8n8.x4.shared.b16 {%0,%1,%2,%3}, [%4];"
        : "=r"(r[0]), "=r"(r[1]), "=r"(r[2]), "=r"(r[3]) : "r"(a));
}
__device__ __forceinline__ void ldsm_x4t(uint32_t* r, uint32_t a) {
    asm volatile("ldmatrix.sync.aligned.m8n8.x4.trans.shared.b16 {%0,%1,%2,%3}, [%4];"
        : "=r"(r[0]), "=r"(r[1]), "=r"(r[2]), "=r"(r[3]) : "r"(a));
}
__device__ __forceinline__ void mma16(float* d, const uint32_t* a, const uint32_t* b) {
    asm("mma.sync.aligned.m16n8k16.row.col.f32.f16.f16.f32 "
        "{%0,%1,%2,%3}, {%4,%5,%6,%7}, {%8,%9}, {%0,%1,%2,%3};"
        : "+f"(d[0]), "+f"(d[1]), "+f"(d[2]), "+f"(d[3])
        : "r"(a[0]), "r"(a[1]), "r"(a[2]), "r"(a[3]), "r"(b[0]), "r"(b[1]));
}

// ---------------------------------------------------------------------------
// Conversion kernels: fp32 -> fp16 staging
// ---------------------------------------------------------------------------
__global__ void cvt_x(const float* __restrict__ X)
{
    const size_t i8 = ((size_t)blockIdx.x * 256 + threadIdx.x) * 8;
    const float4 a = *(const float4*)(X + i8);
    const float4 b = *(const float4*)(X + i8 + 4);
    uint32_t r[4] = { h2bits(a.x, a.y), h2bits(a.z, a.w),
                      h2bits(b.x, b.y), h2bits(b.z, b.w) };
    *(uint4*)(g_Xh + i8) = *(uint4*)r;
}

__global__ void cvt_w(const float* __restrict__ Wq,
                      const float* __restrict__ Wk,
                      const float* __restrict__ Wv)
{
    const int i8 = (blockIdx.x * 256 + threadIdx.x) * 8;   // < 196608
    const int t3 = i8 >> 16;
    const int off = i8 & 65535;
    const float* src = (t3 == 0) ? Wq : (t3 == 1) ? Wk : Wv;
    const float4 a = *(const float4*)(src + off);
    const float4 b = *(const float4*)(src + off + 4);
    uint32_t r[4] = { h2bits(a.x, a.y), h2bits(a.z, a.w),
                      h2bits(b.x, b.y), h2bits(b.z, b.w) };
    *(uint4*)(g_Wh + i8) = *(uint4*)r;
}

// ---------------------------------------------------------------------------
// Kernel 0: precompute combined mask + relative-position bias.
// ---------------------------------------------------------------------------
__global__ void prep_cmb(const float* __restrict__ mask,
                         const float* __restrict__ bt,
                         const int*   __restrict__ ri)
{
    const int idx = blockIdx.x * 256 + threadIdx.x;
    const int p = idx & 4095;
    const int h = (idx >> 12) & 7;
    const int w = idx >> 15;
    g_CMB[idx] = mask[w * 4096 + p] + bt[ri[p] * 8 + h];
}

// ---------------------------------------------------------------------------
// Kernel 1: QKV projection GEMM, fp16 mma + ldmatrix.
//   CTA tile 128x128x32, 8 warps, warp tile 32x64, m16n8k16.
// ---------------------------------------------------------------------------
__global__ __launch_bounds__(256) void qkv_gemm_tc(
    const float* __restrict__ Bq, const float* __restrict__ Bk,
    const float* __restrict__ Bv)
{
    __shared__ __half As[128][40];
    __shared__ __half Bs[128][40];

    const int tid  = threadIdx.x;
    const int m0   = blockIdx.y * 128;
    const int nsel = blockIdx.x;       // 0..5
    const int t3   = nsel >> 1;
    const int nl0  = (nsel & 1) * 128;

    const float* bias = (t3 == 0) ? Bq : (t3 == 1) ? Bk : Bv;
    __half* outp      = (t3 == 0) ? g_Q : (t3 == 1) ? g_K : g_V;
    const __half* Wb  = g_Wh + t3 * (DIM * DIM);

    const int lane = tid & 31;
    const int warp = tid >> 5;
    const int g  = lane >> 2;
    const int tg = lane & 3;
    const int wm = (warp >> 1) * 32;
    const int wn = (warp & 1) * 64;

    // global load mapping: uint4 = 8 halves; rows arow & arow+64
    const int arow = tid >> 2;
    const int acol = (tid & 3) * 8;

    // ldmatrix lane addresses
    const int ra = (lane & 7) + ((lane >> 3) & 1) * 8;
    const int ca = (lane >> 4) * 8;
    const uint32_t aA = smem_u32(&As[wm + ra][ca]);
    const int nb = (lane & 7) + (lane >> 4) * 8;
    const int kb = ((lane >> 3) & 1) * 8;
    const uint32_t aB = smem_u32(&Bs[wn + nb][kb]);

    float acc[2][8][4] = {};

    const __half* xa = g_Xh + (size_t)(m0 + arow) * DIM + acol;
    const __half* xb = Wb + (size_t)(nl0 + arow) * DIM + acol;

    uint4 va0 = *(const uint4*)xa;
    uint4 va1 = *(const uint4*)(xa + 64 * DIM);
    uint4 vb0 = *(const uint4*)xb;
    uint4 vb1 = *(const uint4*)(xb + 64 * DIM);

    #pragma unroll
    for (int kt = 0; kt < 8; kt++) {
        *(uint4*)&As[arow][acol]      = va0;
        *(uint4*)&As[arow + 64][acol] = va1;
        *(uint4*)&Bs[arow][acol]      = vb0;
        *(uint4*)&Bs[arow + 64][acol] = vb1;
        __syncthreads();

        if (kt < 7) {
            const int o = (kt + 1) * 32;
            va0 = *(const uint4*)(xa + o);
            va1 = *(const uint4*)(xa + 64 * DIM + o);
            vb0 = *(const uint4*)(xb + o);
            vb1 = *(const uint4*)(xb + 64 * DIM + o);
        }

        #pragma unroll
        for (int kc = 0; kc < 32; kc += 16) {
            uint32_t afr[2][4];
            ldsm_x4(afr[0], aA + kc * 2);
            ldsm_x4(afr[1], aA + 16 * 80 + kc * 2);
            uint32_t bfr[4][4];
            #pragma unroll
            for (int j = 0; j < 4; j++)
                ldsm_x4(bfr[j], aB + j * 16 * 80 + kc * 2);
            #pragma unroll
            for (int mt = 0; mt < 2; mt++)
                #pragma unroll
                for (int nt = 0; nt < 8; nt++)
                    mma16(acc[mt][nt], afr[mt], &bfr[nt >> 1][(nt & 1) * 2]);
        }
        __syncthreads();
    }

    // epilogue: bias add in fp32, store half2
    #pragma unroll
    for (int nt = 0; nt < 8; nt++) {
        const int c = nl0 + wn + nt * 8 + tg * 2;
        const float b0 = bias[c], b1 = bias[c + 1];
        #pragma unroll
        for (int mt = 0; mt < 2; mt++) {
            const int r = m0 + wm + mt * 16 + g;
            *(uint32_t*)(outp + (size_t)r * DIM + c)       = h2bits(acc[mt][nt][0] + b0, acc[mt][nt][1] + b1);
            *(uint32_t*)(outp + (size_t)(r + 8) * DIM + c) = h2bits(acc[mt][nt][2] + b0, acc[mt][nt][3] + b1);
        }
    }
}

// ---------------------------------------------------------------------------
// Kernel 2: fp16 attention with ldmatrix. CTA = (window, head), 4 warps.
// qs/ks/vs all row-major [64][40] halves; V B-frags via ldmatrix.trans.
// ---------------------------------------------------------------------------
__global__ __launch_bounds__(128) void attn_tc(float* __restrict__ out)
{
    __shared__ __half qs[64 * 40];
    __shared__ __half ks[64 * 40];
    __shared__ __half vs[64 * 40];

    const int b = blockIdx.x;
    const int h = blockIdx.y;
    const int tid  = threadIdx.x;
    const int lane = tid & 31;
    const int warp = tid >> 5;
    const int g  = lane >> 2;
    const int tg = lane & 3;

    // ---- cooperative load: thread = (token row, 16-col half) ----
    const size_t gbase = (size_t)b * (NTOK * DIM) + (size_t)h * HEADDIM;
    {
        const int r  = tid >> 1;
        const int ch = (tid & 1) * 16;
        const size_t go = gbase + (size_t)r * DIM + ch;
        *(uint4*)&qs[r * 40 + ch]     = *(const uint4*)(g_Q + go);
        *(uint4*)&qs[r * 40 + ch + 8] = *(const uint4*)(g_Q + go + 8);
        *(uint4*)&ks[r * 40 + ch]     = *(const uint4*)(g_K + go);
        *(uint4*)&ks[r * 40 + ch + 8] = *(const uint4*)(g_K + go + 8);
        *(uint4*)&vs[r * 40 + ch]     = *(const uint4*)(g_V + go);
        *(uint4*)&vs[r * 40 + ch + 8] = *(const uint4*)(g_V + go + 8);
    }
    __syncthreads();

    // ldmatrix lane addresses
    const int ra = (lane & 7) + ((lane >> 3) & 1) * 8;
    const int ca = (lane >> 4) * 8;
    const uint32_t aQ = smem_u32(&qs[(warp * 16 + ra) * 40 + ca]);
    const int nb = (lane & 7) + (lane >> 4) * 8;
    const int kb = ((lane >> 3) & 1) * 8;
    const uint32_t aK = smem_u32(&ks[nb * 40 + kb]);
    const uint32_t aV = smem_u32(&vs[ra * 40 + ca]);   // trans: rows=tok, col half

    // ---- scores: S = Q K^T (warp rows [16w,+16) x 64 cols) ----
    float sacc[8][4] = {};
    #pragma unroll
    for (int kc = 0; kc < HEADDIM; kc += 16) {
        uint32_t afr[4];
        ldsm_x4(afr, aQ + kc * 2);
        #pragma unroll
        for (int j = 0; j < 4; j++) {
            uint32_t bfr[4];
            ldsm_x4(bfr, aK + j * 16 * 80 + kc * 2);
            mma16(sacc[j * 2],     afr, &bfr[0]);
            mma16(sacc[j * 2 + 1], afr, &bfr[2]);
        }
    }

    // ---- scale + mask/bias into registers ----
    const float scale = 0.17677669529663687f;   // 1/sqrt(32)
    const float* cmb = g_CMB + (((size_t)(b & (MASK_NW - 1)) * HEADS + h) << 12);
    const int r0 = warp * 16 + g;

    float v0[16], v1[16];   // rows r0 / r0+8, cols nt*8 + 2tg + {0,1}
    #pragma unroll
    for (int nt = 0; nt < 8; nt++) {
        const int c0 = nt * 8 + tg * 2;
        const float2 m0v = *(const float2*)(cmb + r0 * 64 + c0);
        const float2 m1v = *(const float2*)(cmb + (r0 + 8) * 64 + c0);
        v0[nt * 2]     = sacc[nt][0] * scale + m0v.x;
        v0[nt * 2 + 1] = sacc[nt][1] * scale + m0v.y;
        v1[nt * 2]     = sacc[nt][2] * scale + m1v.x;
        v1[nt * 2 + 1] = sacc[nt][3] * scale + m1v.y;
    }

    // ---- register softmax (row spread over 4 tg lanes) ----
    {
        float mx0 = v0[0], mx1 = v1[0];
        #pragma unroll
        for (int i = 1; i < 16; i++) { mx0 = fmaxf(mx0, v0[i]); mx1 = fmaxf(mx1, v1[i]); }
        mx0 = fmaxf(mx0, __shfl_xor_sync(0xffffffffu, mx0, 1));
        mx0 = fmaxf(mx0, __shfl_xor_sync(0xffffffffu, mx0, 2));
        mx1 = fmaxf(mx1, __shfl_xor_sync(0xffffffffu, mx1, 1));
        mx1 = fmaxf(mx1, __shfl_xor_sync(0xffffffffu, mx1, 2));

        float s0 = 0.f, s1 = 0.f;
        #pragma unroll
        for (int i = 0; i < 16; i++) {
            v0[i] = __expf(v0[i] - mx0); s0 += v0[i];
            v1[i] = __expf(v1[i] - mx1); s1 += v1[i];
        }
        s0 += __shfl_xor_sync(0xffffffffu, s0, 1);
        s0 += __shfl_xor_sync(0xffffffffu, s0, 2);
        s1 += __shfl_xor_sync(0xffffffffu, s1, 1);
        s1 += __shfl_xor_sync(0xffffffffu, s1, 2);
        const float inv0 = 1.0f / s0, inv1 = 1.0f / s1;
        #pragma unroll
        for (int i = 0; i < 16; i++) { v0[i] *= inv0; v1[i] *= inv1; }
    }

    // ---- PV: O = P(16x64) @ V(64x32); P C-frags -> A-frags by register pack,
    //      V B-frags via ldmatrix.x4.trans (covers 16 k x 16 n per op).
    float oacc[4][4] = {};
    #pragma unroll
    for (int kt = 0; kt < 4; kt++) {
        uint32_t afr[4];
        afr[0] = h2bits(v0[4 * kt],     v0[4 * kt + 1]);
        afr[1] = h2bits(v1[4 * kt],     v1[4 * kt + 1]);
        afr[2] = h2bits(v0[4 * kt + 2], v0[4 * kt + 3]);
        afr[3] = h2bits(v1[4 * kt + 2], v1[4 * kt + 3]);
        #pragma unroll
        for (int p = 0; p < 2; p++) {
            uint32_t bfr[4];
            ldsm_x4t(bfr, aV + kt * 16 * 80 + p * 32);
            mma16(oacc[p * 2],     afr, &bfr[0]);
            mma16(oacc[p * 2 + 1], afr, &bfr[2]);
        }
    }

    // ---- output (fp32) ----
    {
        float* ob = out + gbase;
        #pragma unroll
        for (int nt = 0; nt < 4; nt++) {
            const int c0 = nt * 8 + tg * 2;
            *(float2*)(ob + (size_t)r0 * DIM + c0)       = make_float2(oacc[nt][0], oacc[nt][1]);
            *(float2*)(ob + (size_t)(r0 + 8) * DIM + c0) = make_float2(oacc[nt][2], oacc[nt][3]);
        }
    }
}

// ---------------------------------------------------------------------------
extern "C" void kernel_launch(void* const* d_in, const int* in_sizes, int n_in,
                              void* d_out, int out_size)
{
    const float* hs   = (const float*)d_in[0];
    const float* mask = (const float*)d_in[1];
    const float* wq   = (const float*)d_in[2];
    const float* bq   = (const float*)d_in[3];
    const float* wk   = (const float*)d_in[4];
    const float* bk   = (const float*)d_in[5];
    const float* wv   = (const float*)d_in[6];
    const float* bv   = (const float*)d_in[7];
    const float* bt   = (const float*)d_in[8];
    const int*   ri   = (const int*)d_in[9];
    float* out = (float*)d_out;

    cvt_x<<<(BATCH * NTOK * DIM) / (8 * 256), 256>>>(hs);
    cvt_w<<<(3 * DIM * DIM) / (8 * 256), 256>>>(wq, wk, wv);
    prep_cmb<<<(MASK_NW * HEADS * NTOK * NTOK) / 256, 256>>>(mask, bt, ri);

    dim3 gemm_grid(6, (BATCH * NTOK) / 128);
    qkv_gemm_tc<<<gemm_grid, 256>>>(bq, bk, bv);

    dim3 attn_grid(BATCH, HEADS);
    attn_tc<<<attn_grid, 128>>>(out);
}

// round 8
// speedup vs baseline: 2.0869x; 1.1732x over previous
#include <cuda_runtime.h>
#include <cuda_fp16.h>
#include <cstdint>

#define BATCH   2048
#define NTOK    64
#define DIM     256
#define HEADS   8
#define HEADDIM 32
#define MASK_NW 64

// fp16 staging: X, W (q|k|v), scratch Q/K/V; CMB fp32
__device__ __half g_Xh[(size_t)BATCH * NTOK * DIM];
__device__ __half g_Wh[3 * DIM * DIM];
__device__ __half g_Q[(size_t)BATCH * NTOK * DIM];
__device__ __half g_K[(size_t)BATCH * NTOK * DIM];
__device__ __half g_V[(size_t)BATCH * NTOK * DIM];
__device__ float  g_CMB[(size_t)MASK_NW * HEADS * NTOK * NTOK];

__device__ __forceinline__ uint32_t h2bits(float a, float b) {
    __half2 h = __floats2half2_rn(a, b);
    return *(uint32_t*)&h;
}
__device__ __forceinline__ uint32_t smem_u32(const void* p) {
    return (uint32_t)__cvta_generic_to_shared(p);
}
__device__ __forceinline__ void ldsm_x4(uint32_t* r, uint32_t a) {
    asm volatile("ldmatrix.sync.aligned.m8n8.x4.shared.b16 {%0,%1,%2,%3}, [%4];"
        : "=r"(r[0]), "=r"(r[1]), "=r"(r[2]), "=r"(r[3]) : "r"(a));
}
__device__ __forceinline__ void ldsm_x4t(uint32_t* r, uint32_t a) {
    asm volatile("ldmatrix.sync.aligned.m8n8.x4.trans.shared.b16 {%0,%1,%2,%3}, [%4];"
        : "=r"(r[0]), "=r"(r[1]), "=r"(r[2]), "=r"(r[3]) : "r"(a));
}
__device__ __forceinline__ void mma16(float* d, const uint32_t* a, const uint32_t* b) {
    asm("mma.sync.aligned.m16n8k16.row.col.f32.f16.f16.f32 "
        "{%0,%1,%2,%3}, {%4,%5,%6,%7}, {%8,%9}, {%0,%1,%2,%3};"
        : "+f"(d[0]), "+f"(d[1]), "+f"(d[2]), "+f"(d[3])
        : "r"(a[0]), "r"(a[1]), "r"(a[2]), "r"(a[3]), "r"(b[0]), "r"(b[1]));
}
__device__ __forceinline__ void cp16(uint32_t dst, const void* src) {
    asm volatile("cp.async.cg.shared.global [%0], [%1], 16;" :: "r"(dst), "l"(src));
}
__device__ __forceinline__ void cp_commit() {
    asm volatile("cp.async.commit_group;");
}
template <int N>
__device__ __forceinline__ void cp_wait() {
    asm volatile("cp.async.wait_group %0;" :: "n"(N));
}

// ---------------------------------------------------------------------------
// Conversion kernels: fp32 -> fp16 staging
// ---------------------------------------------------------------------------
__global__ void cvt_x(const float* __restrict__ X)
{
    const size_t i8 = ((size_t)blockIdx.x * 256 + threadIdx.x) * 8;
    const float4 a = *(const float4*)(X + i8);
    const float4 b = *(const float4*)(X + i8 + 4);
    uint32_t r[4] = { h2bits(a.x, a.y), h2bits(a.z, a.w),
                      h2bits(b.x, b.y), h2bits(b.z, b.w) };
    *(uint4*)(g_Xh + i8) = *(uint4*)r;
}

__global__ void cvt_w(const float* __restrict__ Wq,
                      const float* __restrict__ Wk,
                      const float* __restrict__ Wv)
{
    const int i8 = (blockIdx.x * 256 + threadIdx.x) * 8;
    const int t3 = i8 >> 16;
    const int off = i8 & 65535;
    const float* src = (t3 == 0) ? Wq : (t3 == 1) ? Wk : Wv;
    const float4 a = *(const float4*)(src + off);
    const float4 b = *(const float4*)(src + off + 4);
    uint32_t r[4] = { h2bits(a.x, a.y), h2bits(a.z, a.w),
                      h2bits(b.x, b.y), h2bits(b.z, b.w) };
    *(uint4*)(g_Wh + i8) = *(uint4*)r;
}

// ---------------------------------------------------------------------------
// Kernel 0: precompute combined mask + relative-position bias.
// ---------------------------------------------------------------------------
__global__ void prep_cmb(const float* __restrict__ mask,
                         const float* __restrict__ bt,
                         const int*   __restrict__ ri)
{
    const int idx = blockIdx.x * 256 + threadIdx.x;
    const int p = idx & 4095;
    const int h = (idx >> 12) & 7;
    const int w = idx >> 15;
    g_CMB[idx] = mask[w * 4096 + p] + bt[ri[p] * 8 + h];
}

// ---------------------------------------------------------------------------
// Kernel 1: QKV GEMM, fp16 mma + ldmatrix + cp.async double buffering.
//   CTA tile 128x128x32, 8 warps, warp tile 32x64. 2 CTAs/SM.
// ---------------------------------------------------------------------------
__global__ __launch_bounds__(256, 2) void qkv_gemm_tc(
    const float* __restrict__ Bq, const float* __restrict__ Bk,
    const float* __restrict__ Bv)
{
    __shared__ __half As[2][128][40];
    __shared__ __half Bs[2][128][40];

    const int tid  = threadIdx.x;
    const int m0   = blockIdx.y * 128;
    const int nsel = blockIdx.x;       // 0..5
    const int t3   = nsel >> 1;
    const int nl0  = (nsel & 1) * 128;

    const float* bias = (t3 == 0) ? Bq : (t3 == 1) ? Bk : Bv;
    __half* outp      = (t3 == 0) ? g_Q : (t3 == 1) ? g_K : g_V;
    const __half* Wb  = g_Wh + t3 * (DIM * DIM);

    const int lane = tid & 31;
    const int warp = tid >> 5;
    const int g  = lane >> 2;
    const int tg = lane & 3;
    const int wm = (warp >> 1) * 32;
    const int wn = (warp & 1) * 64;

    // cp.async mapping: thread loads 32 consecutive halves of one tile row
    const int lrow = tid >> 1;          // 0..127
    const int lq   = (tid & 1) * 16;    // 0 or 16

    const __half* xa = g_Xh + (size_t)(m0 + lrow) * DIM + lq;
    const __half* xb = Wb + (size_t)(nl0 + lrow) * DIM + lq;
    const uint32_t sa = smem_u32(&As[0][lrow][lq]);
    const uint32_t sb = smem_u32(&Bs[0][lrow][lq]);
    const uint32_t stg = 128 * 40 * 2;  // stage stride in bytes

    // ldmatrix lane addresses
    const int ra = (lane & 7) + ((lane >> 3) & 1) * 8;
    const int ca = (lane >> 4) * 8;
    const uint32_t aA = smem_u32(&As[0][wm + ra][ca]);
    const int nb = (lane & 7) + (lane >> 4) * 8;
    const int kb = ((lane >> 3) & 1) * 8;
    const uint32_t aB = smem_u32(&Bs[0][wn + nb][kb]);

    float acc[2][8][4] = {};

    // prologue: stage 0
    cp16(sa,      xa);
    cp16(sa + 16, xa + 8);
    cp16(sb,      xb);
    cp16(sb + 16, xb + 8);
    cp_commit();

    #pragma unroll
    for (int kt = 0; kt < 8; kt++) {
        const uint32_t s = (kt & 1) * stg;
        if (kt < 7) {
            const uint32_t sn = ((kt + 1) & 1) * stg;
            const int o = (kt + 1) * 32;
            cp16(sa + sn,      xa + o);
            cp16(sa + sn + 16, xa + o + 8);
            cp16(sb + sn,      xb + o);
            cp16(sb + sn + 16, xb + o + 8);
            cp_commit();
            cp_wait<1>();
        } else {
            cp_wait<0>();
        }
        __syncthreads();

        #pragma unroll
        for (int kc = 0; kc < 32; kc += 16) {
            uint32_t afr[2][4];
            ldsm_x4(afr[0], aA + s + kc * 2);
            ldsm_x4(afr[1], aA + s + 16 * 80 + kc * 2);
            uint32_t bfr[4][4];
            #pragma unroll
            for (int j = 0; j < 4; j++)
                ldsm_x4(bfr[j], aB + s + j * 16 * 80 + kc * 2);
            #pragma unroll
            for (int mt = 0; mt < 2; mt++)
                #pragma unroll
                for (int nt = 0; nt < 8; nt++)
                    mma16(acc[mt][nt], afr[mt], &bfr[nt >> 1][(nt & 1) * 2]);
        }
        __syncthreads();   // done reading stage s before it is overwritten
    }

    // epilogue: bias add in fp32, store half2
    #pragma unroll
    for (int nt = 0; nt < 8; nt++) {
        const int c = nl0 + wn + nt * 8 + tg * 2;
        const float b0 = bias[c], b1 = bias[c + 1];
        #pragma unroll
        for (int mt = 0; mt < 2; mt++) {
            const int r = m0 + wm + mt * 16 + g;
            *(uint32_t*)(outp + (size_t)r * DIM + c)       = h2bits(acc[mt][nt][0] + b0, acc[mt][nt][1] + b1);
            *(uint32_t*)(outp + (size_t)(r + 8) * DIM + c) = h2bits(acc[mt][nt][2] + b0, acc[mt][nt][3] + b1);
        }
    }
}

// ---------------------------------------------------------------------------
// Kernel 2: fp16 attention with ldmatrix. CTA = (window, head), 4 warps.
// ---------------------------------------------------------------------------
__global__ __launch_bounds__(128) void attn_tc(float* __restrict__ out)
{
    __shared__ __half qs[64 * 40];
    __shared__ __half ks[64 * 40];
    __shared__ __half vs[64 * 40];

    const int b = blockIdx.x;
    const int h = blockIdx.y;
    const int tid  = threadIdx.x;
    const int lane = tid & 31;
    const int warp = tid >> 5;
    const int g  = lane >> 2;
    const int tg = lane & 3;

    const size_t gbase = (size_t)b * (NTOK * DIM) + (size_t)h * HEADDIM;
    {
        const int r  = tid >> 1;
        const int ch = (tid & 1) * 16;
        const size_t go = gbase + (size_t)r * DIM + ch;
        *(uint4*)&qs[r * 40 + ch]     = *(const uint4*)(g_Q + go);
        *(uint4*)&qs[r * 40 + ch + 8] = *(const uint4*)(g_Q + go + 8);
        *(uint4*)&ks[r * 40 + ch]     = *(const uint4*)(g_K + go);
        *(uint4*)&ks[r * 40 + ch + 8] = *(const uint4*)(g_K + go + 8);
        *(uint4*)&vs[r * 40 + ch]     = *(const uint4*)(g_V + go);
        *(uint4*)&vs[r * 40 + ch + 8] = *(const uint4*)(g_V + go + 8);
    }
    __syncthreads();

    const int ra = (lane & 7) + ((lane >> 3) & 1) * 8;
    const int ca = (lane >> 4) * 8;
    const uint32_t aQ = smem_u32(&qs[(warp * 16 + ra) * 40 + ca]);
    const int nb = (lane & 7) + (lane >> 4) * 8;
    const int kb = ((lane >> 3) & 1) * 8;
    const uint32_t aK = smem_u32(&ks[nb * 40 + kb]);
    const uint32_t aV = smem_u32(&vs[ra * 40 + ca]);

    // ---- scores ----
    float sacc[8][4] = {};
    #pragma unroll
    for (int kc = 0; kc < HEADDIM; kc += 16) {
        uint32_t afr[4];
        ldsm_x4(afr, aQ + kc * 2);
        #pragma unroll
        for (int j = 0; j < 4; j++) {
            uint32_t bfr[4];
            ldsm_x4(bfr, aK + j * 16 * 80 + kc * 2);
            mma16(sacc[j * 2],     afr, &bfr[0]);
            mma16(sacc[j * 2 + 1], afr, &bfr[2]);
        }
    }

    // ---- scale + mask/bias ----
    const float scale = 0.17677669529663687f;
    const float* cmb = g_CMB + (((size_t)(b & (MASK_NW - 1)) * HEADS + h) << 12);
    const int r0 = warp * 16 + g;

    float v0[16], v1[16];
    #pragma unroll
    for (int nt = 0; nt < 8; nt++) {
        const int c0 = nt * 8 + tg * 2;
        const float2 m0v = *(const float2*)(cmb + r0 * 64 + c0);
        const float2 m1v = *(const float2*)(cmb + (r0 + 8) * 64 + c0);
        v0[nt * 2]     = sacc[nt][0] * scale + m0v.x;
        v0[nt * 2 + 1] = sacc[nt][1] * scale + m0v.y;
        v1[nt * 2]     = sacc[nt][2] * scale + m1v.x;
        v1[nt * 2 + 1] = sacc[nt][3] * scale + m1v.y;
    }

    // ---- register softmax ----
    {
        float mx0 = v0[0], mx1 = v1[0];
        #pragma unroll
        for (int i = 1; i < 16; i++) { mx0 = fmaxf(mx0, v0[i]); mx1 = fmaxf(mx1, v1[i]); }
        mx0 = fmaxf(mx0, __shfl_xor_sync(0xffffffffu, mx0, 1));
        mx0 = fmaxf(mx0, __shfl_xor_sync(0xffffffffu, mx0, 2));
        mx1 = fmaxf(mx1, __shfl_xor_sync(0xffffffffu, mx1, 1));
        mx1 = fmaxf(mx1, __shfl_xor_sync(0xffffffffu, mx1, 2));

        float s0 = 0.f, s1 = 0.f;
        #pragma unroll
        for (int i = 0; i < 16; i++) {
            v0[i] = __expf(v0[i] - mx0); s0 += v0[i];
            v1[i] = __expf(v1[i] - mx1); s1 += v1[i];
        }
        s0 += __shfl_xor_sync(0xffffffffu, s0, 1);
        s0 += __shfl_xor_sync(0xffffffffu, s0, 2);
        s1 += __shfl_xor_sync(0xffffffffu, s1, 1);
        s1 += __shfl_xor_sync(0xffffffffu, s1, 2);
        const float inv0 = 1.0f / s0, inv1 = 1.0f / s1;
        #pragma unroll
        for (int i = 0; i < 16; i++) { v0[i] *= inv0; v1[i] *= inv1; }
    }

    // ---- PV ----
    float oacc[4][4] = {};
    #pragma unroll
    for (int kt = 0; kt < 4; kt++) {
        uint32_t afr[4];
        afr[0] = h2bits(v0[4 * kt],     v0[4 * kt + 1]);
        afr[1] = h2bits(v1[4 * kt],     v1[4 * kt + 1]);
        afr[2] = h2bits(v0[4 * kt + 2], v0[4 * kt + 3]);
        afr[3] = h2bits(v1[4 * kt + 2], v1[4 * kt + 3]);
        #pragma unroll
        for (int p = 0; p < 2; p++) {
            uint32_t bfr[4];
            ldsm_x4t(bfr, aV + kt * 16 * 80 + p * 32);
            mma16(oacc[p * 2],     afr, &bfr[0]);
            mma16(oacc[p * 2 + 1], afr, &bfr[2]);
        }
    }

    // ---- output ----
    {
        float* ob = out + gbase;
        #pragma unroll
        for (int nt = 0; nt < 4; nt++) {
            const int c0 = nt * 8 + tg * 2;
            *(float2*)(ob + (size_t)r0 * DIM + c0)       = make_float2(oacc[nt][0], oacc[nt][1]);
            *(float2*)(ob + (size_t)(r0 + 8) * DIM + c0) = make_float2(oacc[nt][2], oacc[nt][3]);
        }
    }
}

// ---------------------------------------------------------------------------
extern "C" void kernel_launch(void* const* d_in, const int* in_sizes, int n_in,
                              void* d_out, int out_size)
{
    const float* hs   = (const float*)d_in[0];
    const float* mask = (const float*)d_in[1];
    const float* wq   = (const float*)d_in[2];
    const float* bq   = (const float*)d_in[3];
    const float* wk   = (const float*)d_in[4];
    const float* bk   = (const float*)d_in[5];
    const float* wv   = (const float*)d_in[6];
    const float* bv   = (const float*)d_in[7];
    const float* bt   = (const float*)d_in[8];
    const int*   ri   = (const int*)d_in[9];
    float* out = (float*)d_out;

    cvt_x<<<(BATCH * NTOK * DIM) / (8 * 256), 256>>>(hs);
    cvt_w<<<(3 * DIM * DIM) / (8 * 256), 256>>>(wq, wk, wv);
    prep_cmb<<<(MASK_NW * HEADS * NTOK * NTOK) / 256, 256>>>(mask, bt, ri);

    dim3 gemm_grid(6, (BATCH * NTOK) / 128);
    qkv_gemm_tc<<<gemm_grid, 256>>>(bq, bk, bv);

    dim3 attn_grid(BATCH, HEADS);
    attn_tc<<<attn_grid, 128>>>(out);
}

// round 9
// speedup vs baseline: 2.2141x; 1.0609x over previous
#include <cuda_runtime.h>
#include <cuda_fp16.h>
#include <cstdint>

#define BATCH   2048
#define NTOK    64
#define DIM     256
#define HEADS   8
#define HEADDIM 32
#define MASK_NW 64

// fp16 staging: X, W (q|k|v), scratch Q/K/V; CMB fp32
__device__ __half g_Xh[(size_t)BATCH * NTOK * DIM];
__device__ __half g_Wh[3 * DIM * DIM];
__device__ __half g_Q[(size_t)BATCH * NTOK * DIM];
__device__ __half g_K[(size_t)BATCH * NTOK * DIM];
__device__ __half g_V[(size_t)BATCH * NTOK * DIM];
__device__ float  g_CMB[(size_t)MASK_NW * HEADS * NTOK * NTOK];

__device__ __forceinline__ uint32_t h2bits(float a, float b) {
    __half2 h = __floats2half2_rn(a, b);
    return *(uint32_t*)&h;
}
__device__ __forceinline__ uint32_t smem_u32(const void* p) {
    return (uint32_t)__cvta_generic_to_shared(p);
}
__device__ __forceinline__ void ldsm_x4(uint32_t* r, uint32_t a) {
    asm volatile("ldmatrix.sync.aligned.m8n8.x4.shared.b16 {%0,%1,%2,%3}, [%4];"
        : "=r"(r[0]), "=r"(r[1]), "=r"(r[2]), "=r"(r[3]) : "r"(a));
}
__device__ __forceinline__ void ldsm_x4t(uint32_t* r, uint32_t a) {
    asm volatile("ldmatrix.sync.aligned.m8n8.x4.trans.shared.b16 {%0,%1,%2,%3}, [%4];"
        : "=r"(r[0]), "=r"(r[1]), "=r"(r[2]), "=r"(r[3]) : "r"(a));
}
__device__ __forceinline__ void mma16(float* d, const uint32_t* a, const uint32_t* b) {
    asm("mma.sync.aligned.m16n8k16.row.col.f32.f16.f16.f32 "
        "{%0,%1,%2,%3}, {%4,%5,%6,%7}, {%8,%9}, {%0,%1,%2,%3};"
        : "+f"(d[0]), "+f"(d[1]), "+f"(d[2]), "+f"(d[3])
        : "r"(a[0]), "r"(a[1]), "r"(a[2]), "r"(a[3]), "r"(b[0]), "r"(b[1]));
}
__device__ __forceinline__ void cp16(uint32_t dst, const void* src) {
    asm volatile("cp.async.cg.shared.global [%0], [%1], 16;" :: "r"(dst), "l"(src));
}
__device__ __forceinline__ void cp_commit() {
    asm volatile("cp.async.commit_group;");
}
template <int N>
__device__ __forceinline__ void cp_wait() {
    asm volatile("cp.async.wait_group %0;" :: "n"(N));
}

// ---------------------------------------------------------------------------
// Conversion kernels: fp32 -> fp16 staging
// ---------------------------------------------------------------------------
__global__ void cvt_x(const float* __restrict__ X)
{
    const size_t i8 = ((size_t)blockIdx.x * 256 + threadIdx.x) * 8;
    const float4 a = *(const float4*)(X + i8);
    const float4 b = *(const float4*)(X + i8 + 4);
    uint32_t r[4] = { h2bits(a.x, a.y), h2bits(a.z, a.w),
                      h2bits(b.x, b.y), h2bits(b.z, b.w) };
    *(uint4*)(g_Xh + i8) = *(uint4*)r;
}

__global__ void cvt_w(const float* __restrict__ Wq,
                      const float* __restrict__ Wk,
                      const float* __restrict__ Wv)
{
    const int i8 = (blockIdx.x * 256 + threadIdx.x) * 8;
    const int t3 = i8 >> 16;
    const int off = i8 & 65535;
    const float* src = (t3 == 0) ? Wq : (t3 == 1) ? Wk : Wv;
    const float4 a = *(const float4*)(src + off);
    const float4 b = *(const float4*)(src + off + 4);
    uint32_t r[4] = { h2bits(a.x, a.y), h2bits(a.z, a.w),
                      h2bits(b.x, b.y), h2bits(b.z, b.w) };
    *(uint4*)(g_Wh + i8) = *(uint4*)r;
}

// ---------------------------------------------------------------------------
// Kernel 0: precompute combined mask + relative-position bias.
// ---------------------------------------------------------------------------
__global__ void prep_cmb(const float* __restrict__ mask,
                         const float* __restrict__ bt,
                         const int*   __restrict__ ri)
{
    const int idx = blockIdx.x * 256 + threadIdx.x;
    const int p = idx & 4095;
    const int h = (idx >> 12) & 7;
    const int w = idx >> 15;
    g_CMB[idx] = mask[w * 4096 + p] + bt[ri[p] * 8 + h];
}

// ---------------------------------------------------------------------------
// Kernel 1: QKV GEMM, fp16 mma + ldmatrix + 3-stage cp.async pipeline.
//   CTA tile 128x128x32, 8 warps, warp tile 32x64. 2 CTAs/SM.
//   ONE __syncthreads per k-iteration (write target last read 1 iter ago).
// ---------------------------------------------------------------------------
__global__ __launch_bounds__(256, 2) void qkv_gemm_tc(
    const float* __restrict__ Bq, const float* __restrict__ Bk,
    const float* __restrict__ Bv)
{
    __shared__ __half As[3][128][40];
    __shared__ __half Bs[3][128][40];

    const int tid  = threadIdx.x;
    const int m0   = blockIdx.y * 128;
    const int nsel = blockIdx.x;       // 0..5
    const int t3   = nsel >> 1;
    const int nl0  = (nsel & 1) * 128;

    const float* bias = (t3 == 0) ? Bq : (t3 == 1) ? Bk : Bv;
    __half* outp      = (t3 == 0) ? g_Q : (t3 == 1) ? g_K : g_V;
    const __half* Wb  = g_Wh + t3 * (DIM * DIM);

    const int lane = tid & 31;
    const int warp = tid >> 5;
    const int g  = lane >> 2;
    const int tg = lane & 3;
    const int wm = (warp >> 1) * 32;
    const int wn = (warp & 1) * 64;

    // cp.async mapping: thread loads 32 consecutive halves of one tile row
    const int lrow = tid >> 1;          // 0..127
    const int lq   = (tid & 1) * 16;    // 0 or 16

    const __half* xa = g_Xh + (size_t)(m0 + lrow) * DIM + lq;
    const __half* xb = Wb + (size_t)(nl0 + lrow) * DIM + lq;
    const uint32_t sa = smem_u32(&As[0][lrow][lq]);
    const uint32_t sb = smem_u32(&Bs[0][lrow][lq]);
    constexpr uint32_t STG = 128 * 40 * 2;  // stage stride in bytes

    // ldmatrix lane addresses
    const int ra = (lane & 7) + ((lane >> 3) & 1) * 8;
    const int ca = (lane >> 4) * 8;
    const uint32_t aA = smem_u32(&As[0][wm + ra][ca]);
    const int nb = (lane & 7) + (lane >> 4) * 8;
    const int kb = ((lane >> 3) & 1) * 8;
    const uint32_t aB = smem_u32(&Bs[0][wn + nb][kb]);

    float acc[2][8][4] = {};

    // prologue: stages 0 and 1
    #pragma unroll
    for (int p = 0; p < 2; p++) {
        const int o = p * 32;
        cp16(sa + p * STG,      xa + o);
        cp16(sa + p * STG + 16, xa + o + 8);
        cp16(sb + p * STG,      xb + o);
        cp16(sb + p * STG + 16, xb + o + 8);
        cp_commit();
    }

    #pragma unroll
    for (int kt = 0; kt < 8; kt++) {
        if (kt < 7) cp_wait<1>(); else cp_wait<0>();
        __syncthreads();

        // issue stage kt+2 (its slot was last read at iteration kt-1)
        if (kt + 2 < 8) {
            const uint32_t sn = ((kt + 2) % 3) * STG;
            const int o = (kt + 2) * 32;
            cp16(sa + sn,      xa + o);
            cp16(sa + sn + 16, xa + o + 8);
            cp16(sb + sn,      xb + o);
            cp16(sb + sn + 16, xb + o + 8);
        }
        cp_commit();   // commit every iteration to keep group accounting uniform

        const uint32_t s = (kt % 3) * STG;
        #pragma unroll
        for (int kc = 0; kc < 32; kc += 16) {
            uint32_t afr[2][4];
            ldsm_x4(afr[0], aA + s + kc * 2);
            ldsm_x4(afr[1], aA + s + 16 * 80 + kc * 2);
            uint32_t bfr[4][4];
            #pragma unroll
            for (int j = 0; j < 4; j++)
                ldsm_x4(bfr[j], aB + s + j * 16 * 80 + kc * 2);
            #pragma unroll
            for (int mt = 0; mt < 2; mt++)
                #pragma unroll
                for (int nt = 0; nt < 8; nt++)
                    mma16(acc[mt][nt], afr[mt], &bfr[nt >> 1][(nt & 1) * 2]);
        }
    }

    // epilogue: bias add in fp32, store half2
    #pragma unroll
    for (int nt = 0; nt < 8; nt++) {
        const int c = nl0 + wn + nt * 8 + tg * 2;
        const float b0 = bias[c], b1 = bias[c + 1];
        #pragma unroll
        for (int mt = 0; mt < 2; mt++) {
            const int r = m0 + wm + mt * 16 + g;
            *(uint32_t*)(outp + (size_t)r * DIM + c)       = h2bits(acc[mt][nt][0] + b0, acc[mt][nt][1] + b1);
            *(uint32_t*)(outp + (size_t)(r + 8) * DIM + c) = h2bits(acc[mt][nt][2] + b0, acc[mt][nt][3] + b1);
        }
    }
}

// ---------------------------------------------------------------------------
// Kernel 2: fp16 attention with ldmatrix. CTA = (window, head), 4 warps.
// ---------------------------------------------------------------------------
__global__ __launch_bounds__(128) void attn_tc(float* __restrict__ out)
{
    __shared__ __half qs[64 * 40];
    __shared__ __half ks[64 * 40];
    __shared__ __half vs[64 * 40];

    const int b = blockIdx.x;
    const int h = blockIdx.y;
    const int tid  = threadIdx.x;
    const int lane = tid & 31;
    const int warp = tid >> 5;
    const int g  = lane >> 2;
    const int tg = lane & 3;

    const size_t gbase = (size_t)b * (NTOK * DIM) + (size_t)h * HEADDIM;
    {
        const int r  = tid >> 1;
        const int ch = (tid & 1) * 16;
        const size_t go = gbase + (size_t)r * DIM + ch;
        *(uint4*)&qs[r * 40 + ch]     = *(const uint4*)(g_Q + go);
        *(uint4*)&qs[r * 40 + ch + 8] = *(const uint4*)(g_Q + go + 8);
        *(uint4*)&ks[r * 40 + ch]     = *(const uint4*)(g_K + go);
        *(uint4*)&ks[r * 40 + ch + 8] = *(const uint4*)(g_K + go + 8);
        *(uint4*)&vs[r * 40 + ch]     = *(const uint4*)(g_V + go);
        *(uint4*)&vs[r * 40 + ch + 8] = *(const uint4*)(g_V + go + 8);
    }
    __syncthreads();

    const int ra = (lane & 7) + ((lane >> 3) & 1) * 8;
    const int ca = (lane >> 4) * 8;
    const uint32_t aQ = smem_u32(&qs[(warp * 16 + ra) * 40 + ca]);
    const int nb = (lane & 7) + (lane >> 4) * 8;
    const int kb = ((lane >> 3) & 1) * 8;
    const uint32_t aK = smem_u32(&ks[nb * 40 + kb]);
    const uint32_t aV = smem_u32(&vs[ra * 40 + ca]);

    // ---- scores ----
    float sacc[8][4] = {};
    #pragma unroll
    for (int kc = 0; kc < HEADDIM; kc += 16) {
        uint32_t afr[4];
        ldsm_x4(afr, aQ + kc * 2);
        #pragma unroll
        for (int j = 0; j < 4; j++) {
            uint32_t bfr[4];
            ldsm_x4(bfr, aK + j * 16 * 80 + kc * 2);
            mma16(sacc[j * 2],     afr, &bfr[0]);
            mma16(sacc[j * 2 + 1], afr, &bfr[2]);
        }
    }

    // ---- scale + mask/bias ----
    const float scale = 0.17677669529663687f;
    const float* cmb = g_CMB + (((size_t)(b & (MASK_NW - 1)) * HEADS + h) << 12);
    const int r0 = warp * 16 + g;

    float v0[16], v1[16];
    #pragma unroll
    for (int nt = 0; nt < 8; nt++) {
        const int c0 = nt * 8 + tg * 2;
        const float2 m0v = *(const float2*)(cmb + r0 * 64 + c0);
        const float2 m1v = *(const float2*)(cmb + (r0 + 8) * 64 + c0);
        v0[nt * 2]     = sacc[nt][0] * scale + m0v.x;
        v0[nt * 2 + 1] = sacc[nt][1] * scale + m0v.y;
        v1[nt * 2]     = sacc[nt][2] * scale + m1v.x;
        v1[nt * 2 + 1] = sacc[nt][3] * scale + m1v.y;
    }

    // ---- register softmax ----
    {
        float mx0 = v0[0], mx1 = v1[0];
        #pragma unroll
        for (int i = 1; i < 16; i++) { mx0 = fmaxf(mx0, v0[i]); mx1 = fmaxf(mx1, v1[i]); }
        mx0 = fmaxf(mx0, __shfl_xor_sync(0xffffffffu, mx0, 1));
        mx0 = fmaxf(mx0, __shfl_xor_sync(0xffffffffu, mx0, 2));
        mx1 = fmaxf(mx1, __shfl_xor_sync(0xffffffffu, mx1, 1));
        mx1 = fmaxf(mx1, __shfl_xor_sync(0xffffffffu, mx1, 2));

        float s0 = 0.f, s1 = 0.f;
        #pragma unroll
        for (int i = 0; i < 16; i++) {
            v0[i] = __expf(v0[i] - mx0); s0 += v0[i];
            v1[i] = __expf(v1[i] - mx1); s1 += v1[i];
        }
        s0 += __shfl_xor_sync(0xffffffffu, s0, 1);
        s0 += __shfl_xor_sync(0xffffffffu, s0, 2);
        s1 += __shfl_xor_sync(0xffffffffu, s1, 1);
        s1 += __shfl_xor_sync(0xffffffffu, s1, 2);
        const float inv0 = 1.0f / s0, inv1 = 1.0f / s1;
        #pragma unroll
        for (int i = 0; i < 16; i++) { v0[i] *= inv0; v1[i] *= inv1; }
    }

    // ---- PV ----
    float oacc[4][4] = {};
    #pragma unroll
    for (int kt = 0; kt < 4; kt++) {
        uint32_t afr[4];
        afr[0] = h2bits(v0[4 * kt],     v0[4 * kt + 1]);
        afr[1] = h2bits(v1[4 * kt],     v1[4 * kt + 1]);
        afr[2] = h2bits(v0[4 * kt + 2], v0[4 * kt + 3]);
        afr[3] = h2bits(v1[4 * kt + 2], v1[4 * kt + 3]);
        #pragma unroll
        for (int p = 0; p < 2; p++) {
            uint32_t bfr[4];
            ldsm_x4t(bfr, aV + kt * 16 * 80 + p * 32);
            mma16(oacc[p * 2],     afr, &bfr[0]);
            mma16(oacc[p * 2 + 1], afr, &bfr[2]);
        }
    }

    // ---- output ----
    {
        float* ob = out + gbase;
        #pragma unroll
        for (int nt = 0; nt < 4; nt++) {
            const int c0 = nt * 8 + tg * 2;
            *(float2*)(ob + (size_t)r0 * DIM + c0)       = make_float2(oacc[nt][0], oacc[nt][1]);
            *(float2*)(ob + (size_t)(r0 + 8) * DIM + c0) = make_float2(oacc[nt][2], oacc[nt][3]);
        }
    }
}

// ---------------------------------------------------------------------------
extern "C" void kernel_launch(void* const* d_in, const int* in_sizes, int n_in,
                              void* d_out, int out_size)
{
    const float* hs   = (const float*)d_in[0];
    const float* mask = (const float*)d_in[1];
    const float* wq   = (const float*)d_in[2];
    const float* bq   = (const float*)d_in[3];
    const float* wk   = (const float*)d_in[4];
    const float* bk   = (const float*)d_in[5];
    const float* wv   = (const float*)d_in[6];
    const float* bv   = (const float*)d_in[7];
    const float* bt   = (const float*)d_in[8];
    const int*   ri   = (const int*)d_in[9];
    float* out = (float*)d_out;

    cvt_x<<<(BATCH * NTOK * DIM) / (8 * 256), 256>>>(hs);
    cvt_w<<<(3 * DIM * DIM) / (8 * 256), 256>>>(wq, wk, wv);
    prep_cmb<<<(MASK_NW * HEADS * NTOK * NTOK) / 256, 256>>>(mask, bt, ri);

    dim3 gemm_grid(6, (BATCH * NTOK) / 128);
    qkv_gemm_tc<<<gemm_grid, 256>>>(bq, bk, bv);

    dim3 attn_grid(BATCH, HEADS);
    attn_tc<<<attn_grid, 128>>>(out);
}

// round 11
// speedup vs baseline: 2.3125x; 1.0445x over previous
#include <cuda_runtime.h>
#include <cuda_fp16.h>
#include <cstdint>

#define BATCH   2048
#define NTOK    64
#define DIM     256
#define HEADS   8
#define HEADDIM 32
#define MASK_NW 64

// fp16 staging: X, W (q|k|v), scratch Q/K/V; CMB fp32
__device__ __half g_Xh[(size_t)BATCH * NTOK * DIM];
__device__ __half g_Wh[3 * DIM * DIM];
__device__ __half g_Q[(size_t)BATCH * NTOK * DIM];
__device__ __half g_K[(size_t)BATCH * NTOK * DIM];
__device__ __half g_V[(size_t)BATCH * NTOK * DIM];
__device__ float  g_CMB[(size_t)MASK_NW * HEADS * NTOK * NTOK];

__device__ __forceinline__ uint32_t h2bits(float a, float b) {
    __half2 h = __floats2half2_rn(a, b);
    return *(uint32_t*)&h;
}
__device__ __forceinline__ uint32_t smem_u32(const void* p) {
    return (uint32_t)__cvta_generic_to_shared(p);
}
__device__ __forceinline__ void ldsm_x4(uint32_t* r, uint32_t a) {
    asm volatile("ldmatrix.sync.aligned.m8n8.x4.shared.b16 {%0,%1,%2,%3}, [%4];"
        : "=r"(r[0]), "=r"(r[1]), "=r"(r[2]), "=r"(r[3]) : "r"(a));
}
__device__ __forceinline__ void ldsm_x4t(uint32_t* r, uint32_t a) {
    asm volatile("ldmatrix.sync.aligned.m8n8.x4.trans.shared.b16 {%0,%1,%2,%3}, [%4];"
        : "=r"(r[0]), "=r"(r[1]), "=r"(r[2]), "=r"(r[3]) : "r"(a));
}
__device__ __forceinline__ void mma16(float* d, const uint32_t* a, const uint32_t* b) {
    asm("mma.sync.aligned.m16n8k16.row.col.f32.f16.f16.f32 "
        "{%0,%1,%2,%3}, {%4,%5,%6,%7}, {%8,%9}, {%0,%1,%2,%3};"
        : "+f"(d[0]), "+f"(d[1]), "+f"(d[2]), "+f"(d[3])
        : "r"(a[0]), "r"(a[1]), "r"(a[2]), "r"(a[3]), "r"(b[0]), "r"(b[1]));
}
__device__ __forceinline__ void cp16(uint32_t dst, const void* src) {
    asm volatile("cp.async.cg.shared.global [%0], [%1], 16;" :: "r"(dst), "l"(src));
}
__device__ __forceinline__ void cp_commit() {
    asm volatile("cp.async.commit_group;");
}
template <int N>
__device__ __forceinline__ void cp_wait() {
    asm volatile("cp.async.wait_group %0;" :: "n"(N));
}

// ---------------------------------------------------------------------------
// Conversion kernels: fp32 -> fp16 staging
// ---------------------------------------------------------------------------
__global__ void cvt_x(const float* __restrict__ X)
{
    const size_t i8 = ((size_t)blockIdx.x * 256 + threadIdx.x) * 8;
    const float4 a = *(const float4*)(X + i8);
    const float4 b = *(const float4*)(X + i8 + 4);
    uint32_t r[4] = { h2bits(a.x, a.y), h2bits(a.z, a.w),
                      h2bits(b.x, b.y), h2bits(b.z, b.w) };
    *(uint4*)(g_Xh + i8) = *(uint4*)r;
}

__global__ void cvt_w(const float* __restrict__ Wq,
                      const float* __restrict__ Wk,
                      const float* __restrict__ Wv)
{
    const int i8 = (blockIdx.x * 256 + threadIdx.x) * 8;
    const int t3 = i8 >> 16;
    const int off = i8 & 65535;
    const float* src = (t3 == 0) ? Wq : (t3 == 1) ? Wk : Wv;
    const float4 a = *(const float4*)(src + off);
    const float4 b = *(const float4*)(src + off + 4);
    uint32_t r[4] = { h2bits(a.x, a.y), h2bits(a.z, a.w),
                      h2bits(b.x, b.y), h2bits(b.z, b.w) };
    *(uint4*)(g_Wh + i8) = *(uint4*)r;
}

// ---------------------------------------------------------------------------
// Kernel 0: precompute combined mask + relative-position bias.
// ---------------------------------------------------------------------------
__global__ void prep_cmb(const float* __restrict__ mask,
                         const float* __restrict__ bt,
                         const int*   __restrict__ ri)
{
    const int idx = blockIdx.x * 256 + threadIdx.x;
    const int p = idx & 4095;
    const int h = (idx >> 12) & 7;
    const int w = idx >> 15;
    g_CMB[idx] = mask[w * 4096 + p] + bt[ri[p] * 8 + h];
}

// ---------------------------------------------------------------------------
// Kernel 1: X-resident QKV GEMM. One CTA per 128-row m-block (1024 CTAs).
//   X tile [128 x 256] fp16 in swizzled smem (loaded once); 6 output slabs
//   stream weight tiles through a 3-stage cp.async pipeline running
//   continuously across slab boundaries. 8 warps, warp tile 32x64. 2 CTA/SM.
//   X swizzle: byte col ^ ((row & 7) << 4)  (row stride 512 B)
// ---------------------------------------------------------------------------
#define GEMM_SMEM (128 * 256 * 2 + 3 * 128 * 40 * 2)   // 96256 B

__global__ __launch_bounds__(256, 2) void qkv_gemm_tc(
    const float* __restrict__ Bq, const float* __restrict__ Bk,
    const float* __restrict__ Bv)
{
    extern __shared__ __half sm[];
    __half* Xs  = sm;                 // 128 x 256, swizzled, 512 B rows
    __half* Bsm = sm + 128 * 256;     // 3 stages x 128 x 40

    const int tid  = threadIdx.x;
    const int m0   = blockIdx.x * 128;
    const int lane = tid & 31;
    const int warp = tid >> 5;
    const int g  = lane >> 2;
    const int tg = lane & 3;
    const int wm = (warp >> 1) * 32;
    const int wn = (warp & 1) * 64;

    const uint32_t XsB = smem_u32(Xs);
    const uint32_t BsB = smem_u32(Bsm);
    constexpr uint32_t BSTG = 128 * 40 * 2;   // B stage stride (bytes)

    // ---- one-time X tile load (swizzled) ----
    {
        const int ar = tid >> 1;            // row 0..127
        const int ah = tid & 1;             // half-row
        const __half* xsrc = g_Xh + (size_t)(m0 + ar) * DIM + ah * 128;
        const uint32_t rbase = XsB + ar * 512;
        const int sw = (ar & 7) << 4;
        #pragma unroll
        for (int i = 0; i < 16; i++) {
            const int col = ah * 256 + i * 16;
            cp16(rbase + (col ^ sw), xsrc + i * 8);
        }
        cp_commit();
    }

    // ---- B stage load: thread = (row, 16-half chunk) -> 2 x cp16 (32 B) ----
    const int br = tid >> 1;
    const int bh = (tid & 1) * 16;          // halves
    const uint32_t bdst = BsB + (br * 40 + bh) * 2;

    auto bsrc = [&](int it) -> const __half* {
        const int nsel = it >> 3, kt = it & 7;
        const int t3 = nsel >> 1, nl0 = (nsel & 1) << 7;
        return g_Wh + t3 * 65536 + (size_t)(nl0 + br) * 256 + kt * 32 + bh;
    };

    // prologue: B stages for it = 0, 1
    {
        const __half* s0 = bsrc(0);
        cp16(bdst,      s0);
        cp16(bdst + 16, s0 + 8);
        cp_commit();
        const __half* s1 = bsrc(1);
        cp16(bdst + BSTG,      s1);
        cp16(bdst + BSTG + 16, s1 + 8);
        cp_commit();
    }

    // ---- ldmatrix lane addresses ----
    const int ra = (lane & 7) + ((lane >> 3) & 1) * 8;
    const int cab = (lane >> 4) * 16;       // bytes (0 or 16)
    uint32_t aArow[2]; int aAsw[2];
    #pragma unroll
    for (int mt = 0; mt < 2; mt++) {
        const int rr = wm + mt * 16 + ra;
        aArow[mt] = XsB + rr * 512;
        aAsw[mt]  = (rr & 7) << 4;
    }
    const int nb = (lane & 7) + (lane >> 4) * 8;
    const int kb = ((lane >> 3) & 1) * 8;
    const uint32_t aB = BsB + ((wn + nb) * 40 + kb) * 2;

    float acc[2][8][4] = {};

    for (int nsel = 0; nsel < 6; nsel++) {
        #pragma unroll
        for (int kt = 0; kt < 8; kt++) {
            const int it = nsel * 8 + kt;
            if (it < 47) cp_wait<1>(); else cp_wait<0>();
            __syncthreads();

            if (it + 2 < 48) {
                const uint32_t sn = ((it + 2) % 3) * BSTG;
                const __half* s2 = bsrc(it + 2);
                cp16(bdst + sn,      s2);
                cp16(bdst + sn + 16, s2 + 8);
            }
            cp_commit();   // uniform group accounting

            const uint32_t s = (it % 3) * BSTG;
            #pragma unroll
            for (int kc = 0; kc < 32; kc += 16) {
                const int akb = (kt * 32 + kc) * 2 + cab;   // A byte col (pre-swizzle)
                uint32_t afr[2][4];
                ldsm_x4(afr[0], aArow[0] + (akb ^ aAsw[0]));
                ldsm_x4(afr[1], aArow[1] + (akb ^ aAsw[1]));
                uint32_t bfr[4][4];
                #pragma unroll
                for (int j = 0; j < 4; j++)
                    ldsm_x4(bfr[j], aB + s + j * 16 * 80 + kc * 2);
                #pragma unroll
                for (int mt = 0; mt < 2; mt++)
                    #pragma unroll
                    for (int nt = 0; nt < 8; nt++)
                        mma16(acc[mt][nt], afr[mt], &bfr[nt >> 1][(nt & 1) * 2]);
            }
        }

        // ---- slab epilogue: bias add + store, reset acc ----
        {
            const int t3  = nsel >> 1;
            const int nl0 = (nsel & 1) << 7;
            const float* bias = (t3 == 0) ? Bq : (t3 == 1) ? Bk : Bv;
            __half* outp      = (t3 == 0) ? g_Q : (t3 == 1) ? g_K : g_V;
            #pragma unroll
            for (int nt = 0; nt < 8; nt++) {
                const int c = nl0 + wn + nt * 8 + tg * 2;
                const float b0 = bias[c], b1 = bias[c + 1];
                #pragma unroll
                for (int mt = 0; mt < 2; mt++) {
                    const int r = m0 + wm + mt * 16 + g;
                    *(uint32_t*)(outp + (size_t)r * DIM + c) =
                        h2bits(acc[mt][nt][0] + b0, acc[mt][nt][1] + b1);
                    *(uint32_t*)(outp + (size_t)(r + 8) * DIM + c) =
                        h2bits(acc[mt][nt][2] + b0, acc[mt][nt][3] + b1);
                    acc[mt][nt][0] = 0.f; acc[mt][nt][1] = 0.f;
                    acc[mt][nt][2] = 0.f; acc[mt][nt][3] = 0.f;
                }
            }
        }
    }
}

// ---------------------------------------------------------------------------
// Kernel 2: fp16 attention with ldmatrix. CTA = (window, head), 4 warps.
// ---------------------------------------------------------------------------
__global__ __launch_bounds__(128) void attn_tc(float* __restrict__ out)
{
    __shared__ __half qs[64 * 40];
    __shared__ __half ks[64 * 40];
    __shared__ __half vs[64 * 40];

    const int b = blockIdx.x;
    const int h = blockIdx.y;
    const int tid  = threadIdx.x;
    const int lane = tid & 31;
    const int warp = tid >> 5;
    const int g  = lane >> 2;
    const int tg = lane & 3;

    const size_t gbase = (size_t)b * (NTOK * DIM) + (size_t)h * HEADDIM;
    {
        const int r  = tid >> 1;
        const int ch = (tid & 1) * 16;
        const size_t go = gbase + (size_t)r * DIM + ch;
        *(uint4*)&qs[r * 40 + ch]     = *(const uint4*)(g_Q + go);
        *(uint4*)&qs[r * 40 + ch + 8] = *(const uint4*)(g_Q + go + 8);
        *(uint4*)&ks[r * 40 + ch]     = *(const uint4*)(g_K + go);
        *(uint4*)&ks[r * 40 + ch + 8] = *(const uint4*)(g_K + go + 8);
        *(uint4*)&vs[r * 40 + ch]     = *(const uint4*)(g_V + go);
        *(uint4*)&vs[r * 40 + ch + 8] = *(const uint4*)(g_V + go + 8);
    }
    __syncthreads();

    const int ra = (lane & 7) + ((lane >> 3) & 1) * 8;
    const int ca = (lane >> 4) * 8;
    const uint32_t aQ = smem_u32(&qs[(warp * 16 + ra) * 40 + ca]);
    const int nb = (lane & 7) + (lane >> 4) * 8;
    const int kb = ((lane >> 3) & 1) * 8;
    const uint32_t aK = smem_u32(&ks[nb * 40 + kb]);
    const uint32_t aV = smem_u32(&vs[ra * 40 + ca]);

    // ---- scores ----
    float sacc[8][4] = {};
    #pragma unroll
    for (int kc = 0; kc < HEADDIM; kc += 16) {
        uint32_t afr[4];
        ldsm_x4(afr, aQ + kc * 2);
        #pragma unroll
        for (int j = 0; j < 4; j++) {
            uint32_t bfr[4];
            ldsm_x4(bfr, aK + j * 16 * 80 + kc * 2);
            mma16(sacc[j * 2],     afr, &bfr[0]);
            mma16(sacc[j * 2 + 1], afr, &bfr[2]);
        }
    }

    // ---- scale + mask/bias ----
    const float scale = 0.17677669529663687f;
    const float* cmb = g_CMB + (((size_t)(b & (MASK_NW - 1)) * HEADS + h) << 12);
    const int r0 = warp * 16 + g;

    float v0[16], v1[16];
    #pragma unroll
    for (int nt = 0; nt < 8; nt++) {
        const int c0 = nt * 8 + tg * 2;
        const float2 m0v = *(const float2*)(cmb + r0 * 64 + c0);
        const float2 m1v = *(const float2*)(cmb + (r0 + 8) * 64 + c0);
        v0[nt * 2]     = sacc[nt][0] * scale + m0v.x;
        v0[nt * 2 + 1] = sacc[nt][1] * scale + m0v.y;
        v1[nt * 2]     = sacc[nt][2] * scale + m1v.x;
        v1[nt * 2 + 1] = sacc[nt][3] * scale + m1v.y;
    }

    // ---- register softmax ----
    {
        float mx0 = v0[0], mx1 = v1[0];
        #pragma unroll
        for (int i = 1; i < 16; i++) { mx0 = fmaxf(mx0, v0[i]); mx1 = fmaxf(mx1, v1[i]); }
        mx0 = fmaxf(mx0, __shfl_xor_sync(0xffffffffu, mx0, 1));
        mx0 = fmaxf(mx0, __shfl_xor_sync(0xffffffffu, mx0, 2));
        mx1 = fmaxf(mx1, __shfl_xor_sync(0xffffffffu, mx1, 1));
        mx1 = fmaxf(mx1, __shfl_xor_sync(0xffffffffu, mx1, 2));

        float s0 = 0.f, s1 = 0.f;
        #pragma unroll
        for (int i = 0; i < 16; i++) {
            v0[i] = __expf(v0[i] - mx0); s0 += v0[i];
            v1[i] = __expf(v1[i] - mx1); s1 += v1[i];
        }
        s0 += __shfl_xor_sync(0xffffffffu, s0, 1);
        s0 += __shfl_xor_sync(0xffffffffu, s0, 2);
        s1 += __shfl_xor_sync(0xffffffffu, s1, 1);
        s1 += __shfl_xor_sync(0xffffffffu, s1, 2);
        const float inv0 = 1.0f / s0, inv1 = 1.0f / s1;
        #pragma unroll
        for (int i = 0; i < 16; i++) { v0[i] *= inv0; v1[i] *= inv1; }
    }

    // ---- PV ----
    float oacc[4][4] = {};
    #pragma unroll
    for (int kt = 0; kt < 4; kt++) {
        uint32_t afr[4];
        afr[0] = h2bits(v0[4 * kt],     v0[4 * kt + 1]);
        afr[1] = h2bits(v1[4 * kt],     v1[4 * kt + 1]);
        afr[2] = h2bits(v0[4 * kt + 2], v0[4 * kt + 3]);
        afr[3] = h2bits(v1[4 * kt + 2], v1[4 * kt + 3]);
        #pragma unroll
        for (int p = 0; p < 2; p++) {
            uint32_t bfr[4];
            ldsm_x4t(bfr, aV + kt * 16 * 80 + p * 32);
            mma16(oacc[p * 2],     afr, &bfr[0]);
            mma16(oacc[p * 2 + 1], afr, &bfr[2]);
        }
    }

    // ---- output ----
    {
        float* ob = out + gbase;
        #pragma unroll
        for (int nt = 0; nt < 4; nt++) {
            const int c0 = nt * 8 + tg * 2;
            *(float2*)(ob + (size_t)r0 * DIM + c0)       = make_float2(oacc[nt][0], oacc[nt][1]);
            *(float2*)(ob + (size_t)(r0 + 8) * DIM + c0) = make_float2(oacc[nt][2], oacc[nt][3]);
        }
    }
}

// ---------------------------------------------------------------------------
extern "C" void kernel_launch(void* const* d_in, const int* in_sizes, int n_in,
                              void* d_out, int out_size)
{
    const float* hs   = (const float*)d_in[0];
    const float* mask = (const float*)d_in[1];
    const float* wq   = (const float*)d_in[2];
    const float* bq   = (const float*)d_in[3];
    const float* wk   = (const float*)d_in[4];
    const float* bk   = (const float*)d_in[5];
    const float* wv   = (const float*)d_in[6];
    const float* bv   = (const float*)d_in[7];
    const float* bt   = (const float*)d_in[8];
    const int*   ri   = (const int*)d_in[9];
    float* out = (float*)d_out;

    static bool attr_set = false;
    if (!attr_set) {
        cudaFuncSetAttribute(qkv_gemm_tc,
                             cudaFuncAttributeMaxDynamicSharedMemorySize, GEMM_SMEM);
        attr_set = true;
    }

    cvt_x<<<(BATCH * NTOK * DIM) / (8 * 256), 256>>>(hs);
    cvt_w<<<(3 * DIM * DIM) / (8 * 256), 256>>>(wq, wk, wv);
    prep_cmb<<<(MASK_NW * HEADS * NTOK * NTOK) / 256, 256>>>(mask, bt, ri);

    qkv_gemm_tc<<<(BATCH * NTOK) / 128, 256, GEMM_SMEM>>>(bq, bk, bv);

    dim3 attn_grid(BATCH, HEADS);
    attn_tc<<<attn_grid, 128>>>(out);
}

// round 12
// speedup vs baseline: 2.3176x; 1.0022x over previous
#include <cuda_runtime.h>
#include <cuda_fp16.h>
#include <cstdint>

#define BATCH   2048
#define NTOK    64
#define DIM     256
#define HEADS   8
#define HEADDIM 32
#define MASK_NW 64

// fp16 staging: X, W (q|k|v), scratch Q/K/V; CMB fp32
__device__ __half g_Xh[(size_t)BATCH * NTOK * DIM];
__device__ __half g_Wh[3 * DIM * DIM];
__device__ __half g_Q[(size_t)BATCH * NTOK * DIM];
__device__ __half g_K[(size_t)BATCH * NTOK * DIM];
__device__ __half g_V[(size_t)BATCH * NTOK * DIM];
__device__ float  g_CMB[(size_t)MASK_NW * HEADS * NTOK * NTOK];

__device__ __forceinline__ uint32_t h2bits(float a, float b) {
    __half2 h = __floats2half2_rn(a, b);
    return *(uint32_t*)&h;
}
__device__ __forceinline__ uint32_t smem_u32(const void* p) {
    return (uint32_t)__cvta_generic_to_shared(p);
}
__device__ __forceinline__ void ldsm_x4(uint32_t* r, uint32_t a) {
    asm volatile("ldmatrix.sync.aligned.m8n8.x4.shared.b16 {%0,%1,%2,%3}, [%4];"
        : "=r"(r[0]), "=r"(r[1]), "=r"(r[2]), "=r"(r[3]) : "r"(a));
}
__device__ __forceinline__ void ldsm_x4t(uint32_t* r, uint32_t a) {
    asm volatile("ldmatrix.sync.aligned.m8n8.x4.trans.shared.b16 {%0,%1,%2,%3}, [%4];"
        : "=r"(r[0]), "=r"(r[1]), "=r"(r[2]), "=r"(r[3]) : "r"(a));
}
__device__ __forceinline__ void mma16(float* d, const uint32_t* a, const uint32_t* b) {
    asm("mma.sync.aligned.m16n8k16.row.col.f32.f16.f16.f32 "
        "{%0,%1,%2,%3}, {%4,%5,%6,%7}, {%8,%9}, {%0,%1,%2,%3};"
        : "+f"(d[0]), "+f"(d[1]), "+f"(d[2]), "+f"(d[3])
        : "r"(a[0]), "r"(a[1]), "r"(a[2]), "r"(a[3]), "r"(b[0]), "r"(b[1]));
}
__device__ __forceinline__ void cp16(uint32_t dst, const void* src) {
    asm volatile("cp.async.cg.shared.global [%0], [%1], 16;" :: "r"(dst), "l"(src));
}
__device__ __forceinline__ void cp_commit() {
    asm volatile("cp.async.commit_group;");
}
template <int N>
__device__ __forceinline__ void cp_wait() {
    asm volatile("cp.async.wait_group %0;" :: "n"(N));
}

// ---------------------------------------------------------------------------
// Kernel 0: one-shot prep. Blocks [0,16384): X fp32->fp16; [16384,16480): W;
// [16480,24672): combined mask + rel-bias.
// ---------------------------------------------------------------------------
__global__ void prep_all(const float* __restrict__ X,
                         const float* __restrict__ Wq,
                         const float* __restrict__ Wk,
                         const float* __restrict__ Wv,
                         const float* __restrict__ mask,
                         const float* __restrict__ bt,
                         const int*   __restrict__ ri)
{
    const int bid = blockIdx.x;
    if (bid < 16384) {
        const size_t i8 = ((size_t)bid * 256 + threadIdx.x) * 8;
        const float4 a = *(const float4*)(X + i8);
        const float4 b = *(const float4*)(X + i8 + 4);
        uint32_t r[4] = { h2bits(a.x, a.y), h2bits(a.z, a.w),
                          h2bits(b.x, b.y), h2bits(b.z, b.w) };
        *(uint4*)(g_Xh + i8) = *(uint4*)r;
    } else if (bid < 16384 + 96) {
        const int i8 = ((bid - 16384) * 256 + threadIdx.x) * 8;
        const int t3 = i8 >> 16;
        const int off = i8 & 65535;
        const float* src = (t3 == 0) ? Wq : (t3 == 1) ? Wk : Wv;
        const float4 a = *(const float4*)(src + off);
        const float4 b = *(const float4*)(src + off + 4);
        uint32_t r[4] = { h2bits(a.x, a.y), h2bits(a.z, a.w),
                          h2bits(b.x, b.y), h2bits(b.z, b.w) };
        *(uint4*)(g_Wh + i8) = *(uint4*)r;
    } else {
        const int idx = (bid - 16480) * 256 + threadIdx.x;
        const int p = idx & 4095;
        const int h = (idx >> 12) & 7;
        const int w = idx >> 15;
        g_CMB[idx] = mask[w * 4096 + p] + bt[ri[p] * 8 + h];
    }
}

// ---------------------------------------------------------------------------
// Kernel 1: X-resident QKV GEMM. One CTA per 128-row m-block (1024 CTAs).
//   X tile [128 x 256] fp16 in swizzled smem (loaded once); 6 output slabs
//   stream weight tiles through a 4-stage cp.async pipeline (prefetch
//   distance 3) running continuously across slab boundaries.
//   8 warps, warp tile 32x64, 2 CTA/SM. Fragments for both kc halves are
//   preloaded before the HMMA block.
//   X swizzle: byte col ^ ((row & 7) << 4)  (row stride 512 B)
// ---------------------------------------------------------------------------
#define GEMM_SMEM (128 * 256 * 2 + 4 * 128 * 40 * 2)   // 106496 B

__global__ __launch_bounds__(256, 2) void qkv_gemm_tc(
    const float* __restrict__ Bq, const float* __restrict__ Bk,
    const float* __restrict__ Bv)
{
    extern __shared__ __half sm[];
    __half* Xs  = sm;                 // 128 x 256, swizzled, 512 B rows
    __half* Bsm = sm + 128 * 256;     // 4 stages x 128 x 40

    const int tid  = threadIdx.x;
    const int m0   = blockIdx.x * 128;
    const int lane = tid & 31;
    const int warp = tid >> 5;
    const int g  = lane >> 2;
    const int tg = lane & 3;
    const int wm = (warp >> 1) * 32;
    const int wn = (warp & 1) * 64;

    const uint32_t XsB = smem_u32(Xs);
    const uint32_t BsB = smem_u32(Bsm);
    constexpr uint32_t BSTG = 128 * 40 * 2;   // B stage stride (bytes)

    // ---- one-time X tile load (swizzled) -> commit group 0 ----
    {
        const int ar = tid >> 1;            // row 0..127
        const int ah = tid & 1;             // half-row
        const __half* xsrc = g_Xh + (size_t)(m0 + ar) * DIM + ah * 128;
        const uint32_t rbase = XsB + ar * 512;
        const int sw = (ar & 7) << 4;
        #pragma unroll
        for (int i = 0; i < 16; i++) {
            const int col = ah * 256 + i * 16;
            cp16(rbase + (col ^ sw), xsrc + i * 8);
        }
        cp_commit();
    }

    // ---- B stage load: thread = (row, 16-half chunk) -> 2 x cp16 (32 B) ----
    const int br = tid >> 1;
    const int bh = (tid & 1) * 16;          // halves
    const uint32_t bdst = BsB + (br * 40 + bh) * 2;

    auto bsrc = [&](int it) -> const __half* {
        const int nsel = it >> 3, kt = it & 7;
        const int t3 = nsel >> 1, nl0 = (nsel & 1) << 7;
        return g_Wh + t3 * 65536 + (size_t)(nl0 + br) * 256 + kt * 32 + bh;
    };

    // prologue: B stages 0,1,2 -> commit groups 1,2,3
    #pragma unroll
    for (int p = 0; p < 3; p++) {
        const __half* sp = bsrc(p);
        cp16(bdst + p * BSTG,      sp);
        cp16(bdst + p * BSTG + 16, sp + 8);
        cp_commit();
    }

    // ---- ldmatrix lane addresses ----
    const int ra = (lane & 7) + ((lane >> 3) & 1) * 8;
    const int cab = (lane >> 4) * 16;       // bytes (0 or 16)
    uint32_t aArow[2]; int aAsw[2];
    #pragma unroll
    for (int mt = 0; mt < 2; mt++) {
        const int rr = wm + mt * 16 + ra;
        aArow[mt] = XsB + rr * 512;
        aAsw[mt]  = (rr & 7) << 4;
    }
    const int nb = (lane & 7) + (lane >> 4) * 8;
    const int kb = ((lane >> 3) & 1) * 8;
    const uint32_t aB = BsB + ((wn + nb) * 40 + kb) * 2;

    float acc[2][8][4] = {};

    for (int nsel = 0; nsel < 6; nsel++) {
        #pragma unroll
        for (int kt = 0; kt < 8; kt++) {
            const int it = nsel * 8 + kt;
            // stage it = group it+1; committed so far = it+4 -> pending 2
            cp_wait<2>();
            __syncthreads();

            if (it + 3 < 48) {
                const uint32_t sn = ((it + 3) & 3) * BSTG;
                const __half* s3 = bsrc(it + 3);
                cp16(bdst + sn,      s3);
                cp16(bdst + sn + 16, s3 + 8);
            }
            cp_commit();   // uniform group accounting

            const uint32_t s = (it & 3) * BSTG;

            // preload fragments for both kc halves, then 64 HMMA
            uint32_t afr[2][2][4];
            uint32_t bfr[2][4][4];
            #pragma unroll
            for (int kcb = 0; kcb < 2; kcb++) {
                const int akb = (kt * 32 + kcb * 16) * 2 + cab;
                ldsm_x4(afr[kcb][0], aArow[0] + (akb ^ aAsw[0]));
                ldsm_x4(afr[kcb][1], aArow[1] + (akb ^ aAsw[1]));
                #pragma unroll
                for (int j = 0; j < 4; j++)
                    ldsm_x4(bfr[kcb][j], aB + s + j * 1280 + kcb * 32);
            }
            #pragma unroll
            for (int kcb = 0; kcb < 2; kcb++)
                #pragma unroll
                for (int mt = 0; mt < 2; mt++)
                    #pragma unroll
                    for (int nt = 0; nt < 8; nt++)
                        mma16(acc[mt][nt], afr[kcb][mt],
                              &bfr[kcb][nt >> 1][(nt & 1) * 2]);
        }

        // ---- slab epilogue: bias add + store, reset acc ----
        {
            const int t3  = nsel >> 1;
            const int nl0 = (nsel & 1) << 7;
            const float* bias = (t3 == 0) ? Bq : (t3 == 1) ? Bk : Bv;
            __half* outp      = (t3 == 0) ? g_Q : (t3 == 1) ? g_K : g_V;
            #pragma unroll
            for (int nt = 0; nt < 8; nt++) {
                const int c = nl0 + wn + nt * 8 + tg * 2;
                const float b0 = bias[c], b1 = bias[c + 1];
                #pragma unroll
                for (int mt = 0; mt < 2; mt++) {
                    const int r = m0 + wm + mt * 16 + g;
                    *(uint32_t*)(outp + (size_t)r * DIM + c) =
                        h2bits(acc[mt][nt][0] + b0, acc[mt][nt][1] + b1);
                    *(uint32_t*)(outp + (size_t)(r + 8) * DIM + c) =
                        h2bits(acc[mt][nt][2] + b0, acc[mt][nt][3] + b1);
                    acc[mt][nt][0] = 0.f; acc[mt][nt][1] = 0.f;
                    acc[mt][nt][2] = 0.f; acc[mt][nt][3] = 0.f;
                }
            }
        }
    }
}

// ---------------------------------------------------------------------------
// Kernel 2: fp16 attention with ldmatrix. CTA = (window, head), 4 warps.
// ---------------------------------------------------------------------------
__global__ __launch_bounds__(128) void attn_tc(float* __restrict__ out)
{
    __shared__ __half qs[64 * 40];
    __shared__ __half ks[64 * 40];
    __shared__ __half vs[64 * 40];

    const int b = blockIdx.x;
    const int h = blockIdx.y;
    const int tid  = threadIdx.x;
    const int lane = tid & 31;
    const int warp = tid >> 5;
    const int g  = lane >> 2;
    const int tg = lane & 3;

    const size_t gbase = (size_t)b * (NTOK * DIM) + (size_t)h * HEADDIM;
    {
        const int r  = tid >> 1;
        const int ch = (tid & 1) * 16;
        const size_t go = gbase + (size_t)r * DIM + ch;
        *(uint4*)&qs[r * 40 + ch]     = *(const uint4*)(g_Q + go);
        *(uint4*)&qs[r * 40 + ch + 8] = *(const uint4*)(g_Q + go + 8);
        *(uint4*)&ks[r * 40 + ch]     = *(const uint4*)(g_K + go);
        *(uint4*)&ks[r * 40 + ch + 8] = *(const uint4*)(g_K + go + 8);
        *(uint4*)&vs[r * 40 + ch]     = *(const uint4*)(g_V + go);
        *(uint4*)&vs[r * 40 + ch + 8] = *(const uint4*)(g_V + go + 8);
    }
    __syncthreads();

    const int ra = (lane & 7) + ((lane >> 3) & 1) * 8;
    const int ca = (lane >> 4) * 8;
    const uint32_t aQ = smem_u32(&qs[(warp * 16 + ra) * 40 + ca]);
    const int nb = (lane & 7) + (lane >> 4) * 8;
    const int kb = ((lane >> 3) & 1) * 8;
    const uint32_t aK = smem_u32(&ks[nb * 40 + kb]);
    const uint32_t aV = smem_u32(&vs[ra * 40 + ca]);

    // ---- scores ----
    float sacc[8][4] = {};
    #pragma unroll
    for (int kc = 0; kc < HEADDIM; kc += 16) {
        uint32_t afr[4];
        ldsm_x4(afr, aQ + kc * 2);
        #pragma unroll
        for (int j = 0; j < 4; j++) {
            uint32_t bfr[4];
            ldsm_x4(bfr, aK + j * 16 * 80 + kc * 2);
            mma16(sacc[j * 2],     afr, &bfr[0]);
            mma16(sacc[j * 2 + 1], afr, &bfr[2]);
        }
    }

    // ---- scale + mask/bias ----
    const float scale = 0.17677669529663687f;
    const float* cmb = g_CMB + (((size_t)(b & (MASK_NW - 1)) * HEADS + h) << 12);
    const int r0 = warp * 16 + g;

    float v0[16], v1[16];
    #pragma unroll
    for (int nt = 0; nt < 8; nt++) {
        const int c0 = nt * 8 + tg * 2;
        const float2 m0v = *(const float2*)(cmb + r0 * 64 + c0);
        const float2 m1v = *(const float2*)(cmb + (r0 + 8) * 64 + c0);
        v0[nt * 2]     = sacc[nt][0] * scale + m0v.x;
        v0[nt * 2 + 1] = sacc[nt][1] * scale + m0v.y;
        v1[nt * 2]     = sacc[nt][2] * scale + m1v.x;
        v1[nt * 2 + 1] = sacc[nt][3] * scale + m1v.y;
    }

    // ---- register softmax ----
    {
        float mx0 = v0[0], mx1 = v1[0];
        #pragma unroll
        for (int i = 1; i < 16; i++) { mx0 = fmaxf(mx0, v0[i]); mx1 = fmaxf(mx1, v1[i]); }
        mx0 = fmaxf(mx0, __shfl_xor_sync(0xffffffffu, mx0, 1));
        mx0 = fmaxf(mx0, __shfl_xor_sync(0xffffffffu, mx0, 2));
        mx1 = fmaxf(mx1, __shfl_xor_sync(0xffffffffu, mx1, 1));
        mx1 = fmaxf(mx1, __shfl_xor_sync(0xffffffffu, mx1, 2));

        float s0 = 0.f, s1 = 0.f;
        #pragma unroll
        for (int i = 0; i < 16; i++) {
            v0[i] = __expf(v0[i] - mx0); s0 += v0[i];
            v1[i] = __expf(v1[i] - mx1); s1 += v1[i];
        }
        s0 += __shfl_xor_sync(0xffffffffu, s0, 1);
        s0 += __shfl_xor_sync(0xffffffffu, s0, 2);
        s1 += __shfl_xor_sync(0xffffffffu, s1, 1);
        s1 += __shfl_xor_sync(0xffffffffu, s1, 2);
        const float inv0 = 1.0f / s0, inv1 = 1.0f / s1;
        #pragma unroll
        for (int i = 0; i < 16; i++) { v0[i] *= inv0; v1[i] *= inv1; }
    }

    // ---- PV ----
    float oacc[4][4] = {};
    #pragma unroll
    for (int kt = 0; kt < 4; kt++) {
        uint32_t afr[4];
        afr[0] = h2bits(v0[4 * kt],     v0[4 * kt + 1]);
        afr[1] = h2bits(v1[4 * kt],     v1[4 * kt + 1]);
        afr[2] = h2bits(v0[4 * kt + 2], v0[4 * kt + 3]);
        afr[3] = h2bits(v1[4 * kt + 2], v1[4 * kt + 3]);
        #pragma unroll
        for (int p = 0; p < 2; p++) {
            uint32_t bfr[4];
            ldsm_x4t(bfr, aV + kt * 16 * 80 + p * 32);
            mma16(oacc[p * 2],     afr, &bfr[0]);
            mma16(oacc[p * 2 + 1], afr, &bfr[2]);
        }
    }

    // ---- output ----
    {
        float* ob = out + gbase;
        #pragma unroll
        for (int nt = 0; nt < 4; nt++) {
            const int c0 = nt * 8 + tg * 2;
            *(float2*)(ob + (size_t)r0 * DIM + c0)       = make_float2(oacc[nt][0], oacc[nt][1]);
            *(float2*)(ob + (size_t)(r0 + 8) * DIM + c0) = make_float2(oacc[nt][2], oacc[nt][3]);
        }
    }
}

// ---------------------------------------------------------------------------
extern "C" void kernel_launch(void* const* d_in, const int* in_sizes, int n_in,
                              void* d_out, int out_size)
{
    const float* hs   = (const float*)d_in[0];
    const float* mask = (const float*)d_in[1];
    const float* wq   = (const float*)d_in[2];
    const float* bq   = (const float*)d_in[3];
    const float* wk   = (const float*)d_in[4];
    const float* bk   = (const float*)d_in[5];
    const float* wv   = (const float*)d_in[6];
    const float* bv   = (const float*)d_in[7];
    const float* bt   = (const float*)d_in[8];
    const int*   ri   = (const int*)d_in[9];
    float* out = (float*)d_out;

    static bool attr_set = false;
    if (!attr_set) {
        cudaFuncSetAttribute(qkv_gemm_tc,
                             cudaFuncAttributeMaxDynamicSharedMemorySize, GEMM_SMEM);
        attr_set = true;
    }

    prep_all<<<24672, 256>>>(hs, wq, wk, wv, mask, bt, ri);

    qkv_gemm_tc<<<(BATCH * NTOK) / 128, 256, GEMM_SMEM>>>(bq, bk, bv);

    dim3 attn_grid(BATCH, HEADS);
    attn_tc<<<attn_grid, 128>>>(out);
}